// round 4
// baseline (speedup 1.0000x reference)
#include <cuda_runtime.h>
#include <cuda_bf16.h>
#include <math.h>

#define NSEQ 8192
#define CDIM 1024
#define HDIM 128

// ---------------------------------------------------------------------------
// Scratch: __device__ globals (no cudaMalloc allowed anywhere)
// ---------------------------------------------------------------------------
__device__ __align__(256) float g_q [NSEQ * HDIM];            //  4 MB
__device__ __align__(256) float g_k [NSEQ * HDIM];            //  4 MB
__device__ __align__(256) float g_v [NSEQ * CDIM];            // 32 MB
__device__ __align__(256) float g_s [(size_t)NSEQ * NSEQ];    // 256 MB
__device__ __align__(256) float g_av[NSEQ * CDIM];            // 32 MB

// ---------------------------------------------------------------------------
// Tiled SGEMM, double-buffered, vectorized shared loads.
// TRANS_B=true : C[M,Nc] = alpha * A[M,K] @ B[Nc,K]^T (+bias)
// TRANS_B=false: C[M,Nc] = alpha * A[M,K] @ B[K,Nc]   (+bias)
// BM=BN=128, BK=16, 256 threads.
// Warp tiling: 8 warps as 4x2 grid of 32x64 warp tiles; lane = (lm,ln) = 4x8,
// each thread computes an 8x8 fragment -> all smem fragment reads are LDS.128.
// ---------------------------------------------------------------------------
template <bool TRANS_B, bool HAS_BIAS>
__global__ void __launch_bounds__(256, 2)
gemm_kernel(const float* __restrict__ A, const float* __restrict__ B,
            const float* __restrict__ bias, float* __restrict__ C,
            int M, int Nc, int K, float alpha)
{
    constexpr int BM = 128, BN = 128, BK = 16;
    __shared__ float4 As4[2][BK * BM / 4];
    __shared__ float4 Bs4[2][BK * BN / 4];
    float* As0 = reinterpret_cast<float*>(As4[0]);
    float* As1 = reinterpret_cast<float*>(As4[1]);
    float* Bs0 = reinterpret_cast<float*>(Bs4[0]);
    float* Bs1 = reinterpret_cast<float*>(Bs4[1]);

    const int tid  = threadIdx.x;
    const int warp = tid >> 5;
    const int lane = tid & 31;
    const int wm = warp >> 1;          // 0..3
    const int wn = warp & 1;           // 0..1
    const int lm = lane >> 3;          // 0..3
    const int ln = lane & 7;           // 0..7
    const int fragRow = wm * 32 + lm * 8;   // row of 8x8 frag in block tile
    const int fragCol = wn * 64 + ln * 8;   // col of 8x8 frag in block tile

    const int rowBase = blockIdx.y * BM;
    const int colBase = blockIdx.x * BN;

    // global-load indices (each thread moves 2 float4 per tile per matrix)
    const int fa0 = tid, fa1 = tid + 256;   // A slots 0..511
    // A: r = slot>>2 (row 0..127), cg = slot&3 (float4 group along k)

    float acc[8][8] = {};

    // ---------------- helpers as lambdas ----------------
    auto ldgA = [&](int k0, float4& va0, float4& va1) {
        va0 = *reinterpret_cast<const float4*>(
            &A[(size_t)(rowBase + (fa0 >> 2)) * K + k0 + (fa0 & 3) * 4]);
        va1 = *reinterpret_cast<const float4*>(
            &A[(size_t)(rowBase + (fa1 >> 2)) * K + k0 + (fa1 & 3) * 4]);
    };
    auto stsA = [&](float* As, const float4& va0, const float4& va1) {
        int r0 = fa0 >> 2, c0 = (fa0 & 3) * 4;
        As[(c0 + 0) * BM + r0] = va0.x;
        As[(c0 + 1) * BM + r0] = va0.y;
        As[(c0 + 2) * BM + r0] = va0.z;
        As[(c0 + 3) * BM + r0] = va0.w;
        int r1 = fa1 >> 2, c1 = (fa1 & 3) * 4;
        As[(c1 + 0) * BM + r1] = va1.x;
        As[(c1 + 1) * BM + r1] = va1.y;
        As[(c1 + 2) * BM + r1] = va1.z;
        As[(c1 + 3) * BM + r1] = va1.w;
    };
    auto ldgB = [&](int k0, float4& vb0, float4& vb1) {
        if (TRANS_B) {
            vb0 = *reinterpret_cast<const float4*>(
                &B[(size_t)(colBase + (fa0 >> 2)) * K + k0 + (fa0 & 3) * 4]);
            vb1 = *reinterpret_cast<const float4*>(
                &B[(size_t)(colBase + (fa1 >> 2)) * K + k0 + (fa1 & 3) * 4]);
        } else {
            vb0 = *reinterpret_cast<const float4*>(
                &B[(size_t)(k0 + (fa0 >> 5)) * Nc + colBase + (fa0 & 31) * 4]);
            vb1 = *reinterpret_cast<const float4*>(
                &B[(size_t)(k0 + (fa1 >> 5)) * Nc + colBase + (fa1 & 31) * 4]);
        }
    };
    auto stsB = [&](float* Bs, const float4& vb0, const float4& vb1) {
        if (TRANS_B) {
            int r0 = fa0 >> 2, c0 = (fa0 & 3) * 4;
            Bs[(c0 + 0) * BN + r0] = vb0.x;
            Bs[(c0 + 1) * BN + r0] = vb0.y;
            Bs[(c0 + 2) * BN + r0] = vb0.z;
            Bs[(c0 + 3) * BN + r0] = vb0.w;
            int r1 = fa1 >> 2, c1 = (fa1 & 3) * 4;
            Bs[(c1 + 0) * BN + r1] = vb1.x;
            Bs[(c1 + 1) * BN + r1] = vb1.y;
            Bs[(c1 + 2) * BN + r1] = vb1.z;
            Bs[(c1 + 3) * BN + r1] = vb1.w;
        } else {
            reinterpret_cast<float4*>(Bs)[(fa0 >> 5) * (BN / 4) + (fa0 & 31)] = vb0;
            reinterpret_cast<float4*>(Bs)[(fa1 >> 5) * (BN / 4) + (fa1 & 31)] = vb1;
        }
    };
    auto compute = [&](const float4* As, const float4* Bs) {
        #pragma unroll
        for (int kk = 0; kk < BK; kk++) {
            float4 a0 = As[(kk * BM + fragRow) >> 2];
            float4 a1 = As[(kk * BM + fragRow + 4) >> 2];
            float4 b0 = Bs[(kk * BN + fragCol) >> 2];
            float4 b1 = Bs[(kk * BN + fragCol + 4) >> 2];
            float ra[8] = {a0.x, a0.y, a0.z, a0.w, a1.x, a1.y, a1.z, a1.w};
            float rb[8] = {b0.x, b0.y, b0.z, b0.w, b1.x, b1.y, b1.z, b1.w};
            #pragma unroll
            for (int i = 0; i < 8; i++)
                #pragma unroll
                for (int j = 0; j < 8; j++)
                    acc[i][j] += ra[i] * rb[j];
        }
    };

    // ---------------- pipelined main loop ----------------
    const int nTiles = K / BK;
    {
        float4 va0, va1, vb0, vb1;
        ldgA(0, va0, va1);
        ldgB(0, vb0, vb1);
        stsA(As0, va0, va1);
        stsB(Bs0, vb0, vb1);
    }
    __syncthreads();

    for (int t = 0; t < nTiles; t++) {
        const int cur = t & 1;
        float4 va0, va1, vb0, vb1;
        const bool more = (t + 1 < nTiles);
        if (more) {
            ldgA((t + 1) * BK, va0, va1);
            ldgB((t + 1) * BK, vb0, vb1);
        }
        compute(cur ? As4[1] : As4[0], cur ? Bs4[1] : Bs4[0]);
        if (more) {
            stsA(cur ? As0 : As1, va0, va1);
            stsB(cur ? Bs0 : Bs1, vb0, vb1);
        }
        __syncthreads();
    }

    // ---------------- epilogue ----------------
    #pragma unroll
    for (int i = 0; i < 8; i++) {
        const int r = rowBase + fragRow + i;
        #pragma unroll
        for (int j = 0; j < 8; j += 4) {
            const int c = colBase + fragCol + j;
            float4 o;
            o.x = alpha * acc[i][j + 0];
            o.y = alpha * acc[i][j + 1];
            o.z = alpha * acc[i][j + 2];
            o.w = alpha * acc[i][j + 3];
            if (HAS_BIAS) {
                o.x += bias[c + 0];
                o.y += bias[c + 1];
                o.z += bias[c + 2];
                o.w += bias[c + 3];
            }
            *reinterpret_cast<float4*>(&C[(size_t)r * Nc + c]) = o;
        }
    }
}

// ---------------------------------------------------------------------------
// Row softmax over NSEQ floats, in place. One block (256 threads) per row.
// ---------------------------------------------------------------------------
__global__ void __launch_bounds__(256)
softmax_kernel(float* __restrict__ S)
{
    const int row = blockIdx.x;
    float4* p = reinterpret_cast<float4*>(S + (size_t)row * NSEQ);
    const int tid = threadIdx.x;

    float4 v[8];
    float mx = -INFINITY;
    #pragma unroll
    for (int i = 0; i < 8; i++) {
        v[i] = p[tid + i * 256];
        mx = fmaxf(mx, fmaxf(fmaxf(v[i].x, v[i].y), fmaxf(v[i].z, v[i].w)));
    }

    __shared__ float red[8];
    __shared__ float bcast;
    const int lane = tid & 31, warp = tid >> 5;

    #pragma unroll
    for (int o = 16; o > 0; o >>= 1) mx = fmaxf(mx, __shfl_xor_sync(~0u, mx, o));
    if (lane == 0) red[warp] = mx;
    __syncthreads();
    if (warp == 0) {
        float m = (lane < 8) ? red[lane] : -INFINITY;
        #pragma unroll
        for (int o = 4; o > 0; o >>= 1) m = fmaxf(m, __shfl_xor_sync(~0u, m, o));
        if (lane == 0) bcast = m;
    }
    __syncthreads();
    mx = bcast;
    __syncthreads();

    float sum = 0.f;
    #pragma unroll
    for (int i = 0; i < 8; i++) {
        v[i].x = expf(v[i].x - mx);
        v[i].y = expf(v[i].y - mx);
        v[i].z = expf(v[i].z - mx);
        v[i].w = expf(v[i].w - mx);
        sum += v[i].x + v[i].y + v[i].z + v[i].w;
    }
    #pragma unroll
    for (int o = 16; o > 0; o >>= 1) sum += __shfl_xor_sync(~0u, sum, o);
    if (lane == 0) red[warp] = sum;
    __syncthreads();
    if (warp == 0) {
        float s = (lane < 8) ? red[lane] : 0.f;
        #pragma unroll
        for (int o = 4; o > 0; o >>= 1) s += __shfl_xor_sync(~0u, s, o);
        if (lane == 0) bcast = s;
    }
    __syncthreads();
    const float inv = 1.f / bcast;

    #pragma unroll
    for (int i = 0; i < 8; i++) {
        v[i].x *= inv; v[i].y *= inv; v[i].z *= inv; v[i].w *= inv;
        p[tid + i * 256] = v[i];
    }
}

// ---------------------------------------------------------------------------
// Launch
// ---------------------------------------------------------------------------
extern "C" void kernel_launch(void* const* d_in, const int* in_sizes, int n_in,
                              void* d_out, int out_size)
{
    const float* x  = (const float*)d_in[0];
    const float* Wq = (const float*)d_in[1];
    const float* bq = (const float*)d_in[2];
    const float* Wk = (const float*)d_in[3];
    const float* bk = (const float*)d_in[4];
    const float* Wv = (const float*)d_in[5];
    const float* bv = (const float*)d_in[6];
    const float* Wo = (const float*)d_in[7];
    const float* bo = (const float*)d_in[8];
    float* out = (float*)d_out;

    float *q, *k, *v, *s, *av;
    cudaGetSymbolAddress((void**)&q,  g_q);
    cudaGetSymbolAddress((void**)&k,  g_k);
    cudaGetSymbolAddress((void**)&v,  g_v);
    cudaGetSymbolAddress((void**)&s,  g_s);
    cudaGetSymbolAddress((void**)&av, g_av);

    const float scale = 1.0f / sqrtf((float)HDIM);
    const dim3 blk(256);

    // q = x @ Wq^T + bq   (8192x128)
    gemm_kernel<true, true><<<dim3(HDIM / 128, NSEQ / 128), blk>>>(
        x, Wq, bq, q, NSEQ, HDIM, CDIM, 1.0f);
    // k = x @ Wk^T + bk
    gemm_kernel<true, true><<<dim3(HDIM / 128, NSEQ / 128), blk>>>(
        x, Wk, bk, k, NSEQ, HDIM, CDIM, 1.0f);
    // v = x @ Wv^T + bv   (8192x1024)
    gemm_kernel<true, true><<<dim3(CDIM / 128, NSEQ / 128), blk>>>(
        x, Wv, bv, v, NSEQ, CDIM, CDIM, 1.0f);
    // S = scale * q @ k^T (8192x8192)
    gemm_kernel<true, false><<<dim3(NSEQ / 128, NSEQ / 128), blk>>>(
        q, k, nullptr, s, NSEQ, NSEQ, HDIM, scale);
    // softmax rows in place
    softmax_kernel<<<NSEQ, blk>>>(s);
    // av = S @ v          (8192x1024)
    gemm_kernel<false, false><<<dim3(CDIM / 128, NSEQ / 128), blk>>>(
        s, v, nullptr, av, NSEQ, CDIM, NSEQ, 1.0f);
    // out = av @ Wo^T + bo
    gemm_kernel<true, true><<<dim3(CDIM / 128, NSEQ / 128), blk>>>(
        av, Wo, bo, out, NSEQ, CDIM, CDIM, 1.0f);
}

// round 6
// speedup vs baseline: 1.6917x; 1.6917x over previous
#include <cuda_runtime.h>
#include <cuda_bf16.h>
#include <math.h>
#include <stdint.h>

#define NSEQ 8192
#define CDIM 1024
#define HDIM 128

// ---------------------------------------------------------------------------
// Scratch (__device__ globals; no cudaMalloc allowed)
// ---------------------------------------------------------------------------
__device__ __align__(256) float g_q [NSEQ * HDIM];            //  4 MB
__device__ __align__(256) float g_k [NSEQ * HDIM];            //  4 MB
__device__ __align__(256) float g_v [NSEQ * CDIM];            // 32 MB
__device__ __align__(256) float g_vT[CDIM * NSEQ];            // 32 MB
__device__ __align__(256) float g_s [(size_t)NSEQ * NSEQ];    // 256 MB
__device__ __align__(256) float g_av[NSEQ * CDIM];            // 32 MB

// ---------------------------------------------------------------------------
// Baseline-PTX tensor-core helpers (sm_80+ features; assemble on plain sm_103)
// ---------------------------------------------------------------------------
__device__ __forceinline__ uint32_t smem_u32(const void* p) {
    uint32_t a;
    asm("{ .reg .u64 t; cvta.to.shared.u64 t, %1; cvt.u32.u64 %0, t; }"
        : "=r"(a) : "l"(p));
    return a;
}
__device__ __forceinline__ void ldm_x4(uint32_t addr, uint32_t* r) {
    asm volatile("ldmatrix.sync.aligned.m8n8.x4.shared.b16 {%0,%1,%2,%3}, [%4];"
        : "=r"(r[0]), "=r"(r[1]), "=r"(r[2]), "=r"(r[3]) : "r"(addr));
}
__device__ __forceinline__ void ldm_x2(uint32_t addr, uint32_t* r) {
    asm volatile("ldmatrix.sync.aligned.m8n8.x2.shared.b16 {%0,%1}, [%2];"
        : "=r"(r[0]), "=r"(r[1]) : "r"(addr));
}
__device__ __forceinline__ void mma16816(float* c, const uint32_t* a, const uint32_t* b) {
    asm volatile("mma.sync.aligned.m16n8k16.row.col.f32.bf16.bf16.f32 "
        "{%0,%1,%2,%3}, {%4,%5,%6,%7}, {%8,%9}, {%0,%1,%2,%3};"
        : "+f"(c[0]), "+f"(c[1]), "+f"(c[2]), "+f"(c[3])
        : "r"(a[0]), "r"(a[1]), "r"(a[2]), "r"(a[3]), "r"(b[0]), "r"(b[1]));
}

// fp32 -> (hi bf16 truncated, lo bf16 rounded) split, packed bf16x2
__device__ __forceinline__ void split4(const float4 v, uint2& hi, uint2& lo) {
    uint32_t bx = __float_as_uint(v.x), by = __float_as_uint(v.y);
    uint32_t bz = __float_as_uint(v.z), bw = __float_as_uint(v.w);
    hi.x = (bx >> 16) | (by & 0xFFFF0000u);
    hi.y = (bz >> 16) | (bw & 0xFFFF0000u);
    float lx = v.x - __uint_as_float(bx & 0xFFFF0000u);
    float ly = v.y - __uint_as_float(by & 0xFFFF0000u);
    float lz = v.z - __uint_as_float(bz & 0xFFFF0000u);
    float lw = v.w - __uint_as_float(bw & 0xFFFF0000u);
    asm("cvt.rn.bf16x2.f32 %0, %1, %2;" : "=r"(lo.x) : "f"(ly), "f"(lx));
    asm("cvt.rn.bf16x2.f32 %0, %1, %2;" : "=r"(lo.y) : "f"(lw), "f"(lz));
}

// ---------------------------------------------------------------------------
// Split-bf16 HMMA GEMM: C[M,Nc] = alpha * A[M,K] @ B[Nc,K]^T (+bias)
// CTA tile 128x128, BK=64, 256 threads, warps 2(m) x 4(n) => warp tile 64x32.
// 3 MMA passes (AhBh + AhBl + AlBh) accumulate in fp32 fragments.
// Smem rows padded to 72 bf16 (144 B) => ldmatrix conflict-free.
// ---------------------------------------------------------------------------
#define SROW   72                       // bf16 elems per smem row (64 + 8 pad)
#define TILE_B (128 * SROW * 2)         // 18432 B per tile
#define SMEM_SZ (4 * TILE_B)            // Ah, Al, Bh, Bl

template <bool HAS_BIAS>
__global__ void __launch_bounds__(256)
hmma_gemm(const float* __restrict__ A, const float* __restrict__ B,
          const float* __restrict__ bias, float* __restrict__ C,
          int M, int Nc, int K, float alpha)
{
    extern __shared__ __align__(256) char smem[];
    char* Ah = smem;
    char* Al = smem + TILE_B;
    char* Bh = smem + 2 * TILE_B;
    char* Bl = smem + 3 * TILE_B;
    const uint32_t uAh = smem_u32(Ah), uAl = smem_u32(Al);
    const uint32_t uBh = smem_u32(Bh), uBl = smem_u32(Bl);

    const int tid  = threadIdx.x;
    const int warp = tid >> 5;
    const int lane = tid & 31;
    const int warp_m = warp >> 2;            // 0..1
    const int warp_n = warp & 3;             // 0..3
    const int mBase  = warp_m * 64;          // warp-tile row in CTA tile
    const int nBase  = warp_n * 32;          // warp-tile col in CTA tile

    const int rowBase = blockIdx.y * 128;
    const int colBase = blockIdx.x * 128;

    // ldmatrix per-lane byte offsets (within a tile)
    const int aRow = (lane & 15);            // + mBase + mt*16
    const int aCol8 = 8 * (lane >> 4);       // + kcol
    const int bRow = (lane & 7);             // + nBase + nt*8
    const int bCol8 = 8 * ((lane >> 3) & 1); // + kcol

    float acc[4][4][4] = {};                 // [mt][nt][frag]

    const int nst = K / 64;
    for (int t = 0; t < nst; t++) {
        const int k0 = t * 64;
        // ---------------- stage: LDG fp32 -> split -> STS bf16 ----------------
        #pragma unroll
        for (int i = 0; i < 8; i++) {
            const int f   = tid + i * 256;   // 0..2047 float4 slots
            const int row = f >> 4;          // 0..127
            const int c4  = f & 15;          // 0..15 (float4 along K)
            const int off = row * (SROW * 2) + c4 * 8;  // byte offset (4 bf16)

            float4 va = *reinterpret_cast<const float4*>(
                &A[(size_t)(rowBase + row) * K + k0 + c4 * 4]);
            uint2 h, l;
            split4(va, h, l);
            *reinterpret_cast<uint2*>(Ah + off) = h;
            *reinterpret_cast<uint2*>(Al + off) = l;

            float4 vb = *reinterpret_cast<const float4*>(
                &B[(size_t)(colBase + row) * K + k0 + c4 * 4]);
            split4(vb, h, l);
            *reinterpret_cast<uint2*>(Bh + off) = h;
            *reinterpret_cast<uint2*>(Bl + off) = l;
        }
        __syncthreads();

        // ---------------- compute: 4 x k16 steps ----------------
        #pragma unroll
        for (int kk = 0; kk < 4; kk++) {
            const int kcol = kk * 16;
            // B fragments for all 4 n-tiles (hi & lo)
            uint32_t bh[4][2], bl[4][2];
            #pragma unroll
            for (int nt = 0; nt < 4; nt++) {
                const uint32_t boff =
                    (uint32_t)((nBase + nt * 8 + bRow) * (SROW * 2) +
                               (kcol + bCol8) * 2);
                ldm_x2(uBh + boff, bh[nt]);
                ldm_x2(uBl + boff, bl[nt]);
            }
            #pragma unroll
            for (int mt = 0; mt < 4; mt++) {
                const uint32_t aoff =
                    (uint32_t)((mBase + mt * 16 + aRow) * (SROW * 2) +
                               (kcol + aCol8) * 2);
                uint32_t ah[4], al[4];
                ldm_x4(uAh + aoff, ah);
                ldm_x4(uAl + aoff, al);
                #pragma unroll
                for (int nt = 0; nt < 4; nt++) {
                    mma16816(acc[mt][nt], ah, bh[nt]);
                    mma16816(acc[mt][nt], ah, bl[nt]);
                    mma16816(acc[mt][nt], al, bh[nt]);
                }
            }
        }
        __syncthreads();
    }

    // ---------------- epilogue ----------------
    #pragma unroll
    for (int mt = 0; mt < 4; mt++) {
        #pragma unroll
        for (int nt = 0; nt < 4; nt++) {
            const int r0 = rowBase + mBase + mt * 16 + (lane >> 2);
            const int c0 = colBase + nBase + nt * 8 + 2 * (lane & 3);
            float2 o0, o1;
            o0.x = alpha * acc[mt][nt][0];
            o0.y = alpha * acc[mt][nt][1];
            o1.x = alpha * acc[mt][nt][2];
            o1.y = alpha * acc[mt][nt][3];
            if (HAS_BIAS) {
                const float2 bb = *reinterpret_cast<const float2*>(&bias[c0]);
                o0.x += bb.x; o0.y += bb.y;
                o1.x += bb.x; o1.y += bb.y;
            }
            *reinterpret_cast<float2*>(&C[(size_t)r0 * Nc + c0]) = o0;
            *reinterpret_cast<float2*>(&C[(size_t)(r0 + 8) * Nc + c0]) = o1;
        }
    }
}

// ---------------------------------------------------------------------------
// v[NSEQ,CDIM] -> vT[CDIM,NSEQ] tiled transpose
// ---------------------------------------------------------------------------
__global__ void __launch_bounds__(256)
transpose_kernel(const float* __restrict__ in, float* __restrict__ out)
{
    __shared__ float t[32][33];
    const int c = blockIdx.x * 32 + threadIdx.x;     // CDIM index
    const int r = blockIdx.y * 32 + threadIdx.y;     // NSEQ index
    #pragma unroll
    for (int j = 0; j < 32; j += 8)
        t[threadIdx.y + j][threadIdx.x] = in[(size_t)(r + j) * CDIM + c];
    __syncthreads();
    const int c2 = blockIdx.y * 32 + threadIdx.x;    // NSEQ index
    const int r2 = blockIdx.x * 32 + threadIdx.y;    // CDIM index
    #pragma unroll
    for (int j = 0; j < 32; j += 8)
        out[(size_t)(r2 + j) * NSEQ + c2] = t[threadIdx.x][threadIdx.y + j];
}

// ---------------------------------------------------------------------------
// Row softmax over NSEQ floats, in place. One block (256 threads) per row.
// ---------------------------------------------------------------------------
__global__ void __launch_bounds__(256)
softmax_kernel(float* __restrict__ S)
{
    const int row = blockIdx.x;
    float4* p = reinterpret_cast<float4*>(S + (size_t)row * NSEQ);
    const int tid = threadIdx.x;

    float4 v[8];
    float mx = -INFINITY;
    #pragma unroll
    for (int i = 0; i < 8; i++) {
        v[i] = p[tid + i * 256];
        mx = fmaxf(mx, fmaxf(fmaxf(v[i].x, v[i].y), fmaxf(v[i].z, v[i].w)));
    }

    __shared__ float red[8];
    __shared__ float bcast;
    const int lane = tid & 31, warp = tid >> 5;

    #pragma unroll
    for (int o = 16; o > 0; o >>= 1) mx = fmaxf(mx, __shfl_xor_sync(~0u, mx, o));
    if (lane == 0) red[warp] = mx;
    __syncthreads();
    if (warp == 0) {
        float m = (lane < 8) ? red[lane] : -INFINITY;
        #pragma unroll
        for (int o = 4; o > 0; o >>= 1) m = fmaxf(m, __shfl_xor_sync(~0u, m, o));
        if (lane == 0) bcast = m;
    }
    __syncthreads();
    mx = bcast;
    __syncthreads();

    float sum = 0.f;
    #pragma unroll
    for (int i = 0; i < 8; i++) {
        v[i].x = expf(v[i].x - mx);
        v[i].y = expf(v[i].y - mx);
        v[i].z = expf(v[i].z - mx);
        v[i].w = expf(v[i].w - mx);
        sum += v[i].x + v[i].y + v[i].z + v[i].w;
    }
    #pragma unroll
    for (int o = 16; o > 0; o >>= 1) sum += __shfl_xor_sync(~0u, sum, o);
    if (lane == 0) red[warp] = sum;
    __syncthreads();
    if (warp == 0) {
        float s = (lane < 8) ? red[lane] : 0.f;
        #pragma unroll
        for (int o = 4; o > 0; o >>= 1) s += __shfl_xor_sync(~0u, s, o);
        if (lane == 0) bcast = s;
    }
    __syncthreads();
    const float inv = 1.f / bcast;

    #pragma unroll
    for (int i = 0; i < 8; i++) {
        v[i].x *= inv; v[i].y *= inv; v[i].z *= inv; v[i].w *= inv;
        p[tid + i * 256] = v[i];
    }
}

// ---------------------------------------------------------------------------
// Launch
// ---------------------------------------------------------------------------
extern "C" void kernel_launch(void* const* d_in, const int* in_sizes, int n_in,
                              void* d_out, int out_size)
{
    const float* x  = (const float*)d_in[0];
    const float* Wq = (const float*)d_in[1];
    const float* bq = (const float*)d_in[2];
    const float* Wk = (const float*)d_in[3];
    const float* bk = (const float*)d_in[4];
    const float* Wv = (const float*)d_in[5];
    const float* bv = (const float*)d_in[6];
    const float* Wo = (const float*)d_in[7];
    const float* bo = (const float*)d_in[8];
    float* out = (float*)d_out;

    float *q, *k, *v, *vT, *s, *av;
    cudaGetSymbolAddress((void**)&q,  g_q);
    cudaGetSymbolAddress((void**)&k,  g_k);
    cudaGetSymbolAddress((void**)&v,  g_v);
    cudaGetSymbolAddress((void**)&vT, g_vT);
    cudaGetSymbolAddress((void**)&s,  g_s);
    cudaGetSymbolAddress((void**)&av, g_av);

    cudaFuncSetAttribute(hmma_gemm<true>,
                         cudaFuncAttributeMaxDynamicSharedMemorySize, SMEM_SZ);
    cudaFuncSetAttribute(hmma_gemm<false>,
                         cudaFuncAttributeMaxDynamicSharedMemorySize, SMEM_SZ);

    const float scale = 1.0f / sqrtf((float)HDIM);
    const dim3 blk(256);

    // q = x @ Wq^T + bq   (8192x128)
    hmma_gemm<true><<<dim3(HDIM / 128, NSEQ / 128), blk, SMEM_SZ>>>(
        x, Wq, bq, q, NSEQ, HDIM, CDIM, 1.0f);
    // k = x @ Wk^T + bk
    hmma_gemm<true><<<dim3(HDIM / 128, NSEQ / 128), blk, SMEM_SZ>>>(
        x, Wk, bk, k, NSEQ, HDIM, CDIM, 1.0f);
    // v = x @ Wv^T + bv   (8192x1024)
    hmma_gemm<true><<<dim3(CDIM / 128, NSEQ / 128), blk, SMEM_SZ>>>(
        x, Wv, bv, v, NSEQ, CDIM, CDIM, 1.0f);
    // vT = v^T
    transpose_kernel<<<dim3(CDIM / 32, NSEQ / 32), dim3(32, 8)>>>(v, vT);
    // S = scale * q @ k^T (8192x8192)
    hmma_gemm<false><<<dim3(NSEQ / 128, NSEQ / 128), blk, SMEM_SZ>>>(
        q, k, nullptr, s, NSEQ, NSEQ, HDIM, scale);
    // softmax rows in place
    softmax_kernel<<<NSEQ, blk>>>(s);
    // av = S @ v = S @ vT^T  (8192x1024)
    hmma_gemm<false><<<dim3(CDIM / 128, NSEQ / 128), blk, SMEM_SZ>>>(
        s, vT, nullptr, av, NSEQ, CDIM, NSEQ, 1.0f);
    // out = av @ Wo^T + bo
    hmma_gemm<true><<<dim3(CDIM / 128, NSEQ / 128), blk, SMEM_SZ>>>(
        av, Wo, bo, out, NSEQ, CDIM, CDIM, 1.0f);
}

// round 8
// speedup vs baseline: 2.0027x; 1.1838x over previous
#include <cuda_runtime.h>
#include <cuda_bf16.h>
#include <math.h>
#include <stdint.h>

#define NSEQ 8192
#define CDIM 1024
#define HDIM 128

// ---------------------------------------------------------------------------
// Scratch (__device__ globals; no cudaMalloc allowed)
// ---------------------------------------------------------------------------
__device__ __align__(256) __nv_bfloat16 g_xh [NSEQ * CDIM];
__device__ __align__(256) __nv_bfloat16 g_xl [NSEQ * CDIM];
__device__ __align__(256) __nv_bfloat16 g_Wqh[HDIM * CDIM];
__device__ __align__(256) __nv_bfloat16 g_Wql[HDIM * CDIM];
__device__ __align__(256) __nv_bfloat16 g_Wkh[HDIM * CDIM];
__device__ __align__(256) __nv_bfloat16 g_Wkl[HDIM * CDIM];
__device__ __align__(256) __nv_bfloat16 g_Wvh[CDIM * CDIM];
__device__ __align__(256) __nv_bfloat16 g_Wvl[CDIM * CDIM];
__device__ __align__(256) __nv_bfloat16 g_Woh[CDIM * CDIM];
__device__ __align__(256) __nv_bfloat16 g_Wol[CDIM * CDIM];
__device__ __align__(256) __nv_bfloat16 g_qh [NSEQ * HDIM];
__device__ __align__(256) __nv_bfloat16 g_ql [NSEQ * HDIM];
__device__ __align__(256) __nv_bfloat16 g_kh [NSEQ * HDIM];
__device__ __align__(256) __nv_bfloat16 g_kl [NSEQ * HDIM];
__device__ __align__(256) float         g_v  [NSEQ * CDIM];            // 32 MB
__device__ __align__(256) __nv_bfloat16 g_vTh[CDIM * NSEQ];
__device__ __align__(256) __nv_bfloat16 g_vTl[CDIM * NSEQ];
__device__ __align__(256) float         g_s  [(size_t)NSEQ * NSEQ];    // 256 MB
__device__ __align__(256) __nv_bfloat16 g_sh [(size_t)NSEQ * NSEQ];    // 128 MB
__device__ __align__(256) __nv_bfloat16 g_sl [(size_t)NSEQ * NSEQ];    // 128 MB
__device__ __align__(256) __nv_bfloat16 g_avh[NSEQ * CDIM];
__device__ __align__(256) __nv_bfloat16 g_avl[NSEQ * CDIM];

// ---------------------------------------------------------------------------
// Helpers (baseline PTX only; assembles for plain sm_103)
// ---------------------------------------------------------------------------
__device__ __forceinline__ uint32_t smem_u32(const void* p) {
    uint32_t a;
    asm("{ .reg .u64 t; cvta.to.shared.u64 t, %1; cvt.u32.u64 %0, t; }"
        : "=r"(a) : "l"(p));
    return a;
}
__device__ __forceinline__ void ldm_x4(uint32_t addr, uint32_t* r) {
    asm volatile("ldmatrix.sync.aligned.m8n8.x4.shared.b16 {%0,%1,%2,%3}, [%4];"
        : "=r"(r[0]), "=r"(r[1]), "=r"(r[2]), "=r"(r[3]) : "r"(addr));
}
__device__ __forceinline__ void ldm_x2(uint32_t addr, uint32_t* r) {
    asm volatile("ldmatrix.sync.aligned.m8n8.x2.shared.b16 {%0,%1}, [%2];"
        : "=r"(r[0]), "=r"(r[1]) : "r"(addr));
}
__device__ __forceinline__ void mma16816(float* c, const uint32_t* a, const uint32_t* b) {
    asm volatile("mma.sync.aligned.m16n8k16.row.col.f32.bf16.bf16.f32 "
        "{%0,%1,%2,%3}, {%4,%5,%6,%7}, {%8,%9}, {%0,%1,%2,%3};"
        : "+f"(c[0]), "+f"(c[1]), "+f"(c[2]), "+f"(c[3])
        : "r"(a[0]), "r"(a[1]), "r"(a[2]), "r"(a[3]), "r"(b[0]), "r"(b[1]));
}
__device__ __forceinline__ void cp16(uint32_t dst, const void* src) {
    asm volatile("cp.async.cg.shared.global [%0], [%1], 16;"
        :: "r"(dst), "l"(src) : "memory");
}

// fp32 -> (hi bf16 truncated, lo bf16 rounded) split, packed bf16x2
__device__ __forceinline__ void split4(const float4 v, uint2& hi, uint2& lo) {
    uint32_t bx = __float_as_uint(v.x), by = __float_as_uint(v.y);
    uint32_t bz = __float_as_uint(v.z), bw = __float_as_uint(v.w);
    hi.x = (bx >> 16) | (by & 0xFFFF0000u);
    hi.y = (bz >> 16) | (bw & 0xFFFF0000u);
    float lx = v.x - __uint_as_float(bx & 0xFFFF0000u);
    float ly = v.y - __uint_as_float(by & 0xFFFF0000u);
    float lz = v.z - __uint_as_float(bz & 0xFFFF0000u);
    float lw = v.w - __uint_as_float(bw & 0xFFFF0000u);
    asm("cvt.rn.bf16x2.f32 %0, %1, %2;" : "=r"(lo.x) : "f"(ly), "f"(lx));
    asm("cvt.rn.bf16x2.f32 %0, %1, %2;" : "=r"(lo.y) : "f"(lw), "f"(lz));
}
__device__ __forceinline__ void split2(float a, float b, uint32_t& hi, uint32_t& lo) {
    uint32_t ba = __float_as_uint(a), bb = __float_as_uint(b);
    hi = (ba >> 16) | (bb & 0xFFFF0000u);
    float la = a - __uint_as_float(ba & 0xFFFF0000u);
    float lb = b - __uint_as_float(bb & 0xFFFF0000u);
    asm("cvt.rn.bf16x2.f32 %0, %1, %2;" : "=r"(lo) : "f"(lb), "f"(la));
}

// ---------------------------------------------------------------------------
// Elementwise fp32 -> bf16 hi/lo split
// ---------------------------------------------------------------------------
__global__ void __launch_bounds__(256)
split_kernel(const float* __restrict__ in, __nv_bfloat16* __restrict__ oh,
             __nv_bfloat16* __restrict__ ol, int n4)
{
    const int i = blockIdx.x * 256 + threadIdx.x;
    if (i >= n4) return;
    float4 v = reinterpret_cast<const float4*>(in)[i];
    uint2 h, l;
    split4(v, h, l);
    reinterpret_cast<uint2*>(oh)[i] = h;
    reinterpret_cast<uint2*>(ol)[i] = l;
}

// ---------------------------------------------------------------------------
// Split-bf16 HMMA GEMM with cp.async double-buffered pipeline.
//   C = alpha * A[M,K] @ B[Nc,K]^T (+bias)
// Inputs pre-split bf16 (K-contiguous). Output fp32 or bf16 hi/lo.
// CTA 128x128, BK=64, 256 threads, warps 2x4 (warp tile 64x32), 3 MMA passes.
// ---------------------------------------------------------------------------
#define SROW    72                         // bf16 per smem row (64 + 8 pad)
#define TILE_B  (128 * SROW * 2)           // 18432 B
#define STAGE_B (4 * TILE_B)               // Ah, Al, Bh, Bl = 73728 B
#define SMEM_SZ (2 * STAGE_B)              // double buffer = 147456 B

template <bool HAS_BIAS, bool SPLIT_OUT>
__global__ void __launch_bounds__(256)
hmma_gemm(const __nv_bfloat16* __restrict__ Agh, const __nv_bfloat16* __restrict__ Agl,
          const __nv_bfloat16* __restrict__ Bgh, const __nv_bfloat16* __restrict__ Bgl,
          const float* __restrict__ bias,
          float* __restrict__ Cf,
          __nv_bfloat16* __restrict__ Ch, __nv_bfloat16* __restrict__ Cl,
          int M, int Nc, int K, float alpha)
{
    extern __shared__ __align__(256) char smem[];
    const uint32_t sbase = smem_u32(smem);

    const int tid  = threadIdx.x;
    const int warp = tid >> 5;
    const int lane = tid & 31;
    const int warp_m = warp >> 2;            // 0..1
    const int warp_n = warp & 3;             // 0..3
    const int mBase  = warp_m * 64;
    const int nBase  = warp_n * 32;

    const int rowBase = blockIdx.y * 128;
    const int colBase = blockIdx.x * 128;

    // ldmatrix per-lane offsets
    const int aRow  = (lane & 15);
    const int aCol8 = 8 * (lane >> 4);
    const int bRow  = (lane & 7);
    const int bCol8 = 8 * ((lane >> 3) & 1);

    // cp.async mapping: per tile 128 rows x 8 chunks of 16B
    const int cRow = tid >> 1;               // 0..127 (2 threads per row)
    const int cCh0 = (tid & 1) * 4;          // chunks 0..3 or 4..7

    auto prefetch = [&](int t, int buf) {
        const uint32_t base = sbase + buf * STAGE_B;
        const int k0 = t * 64;
        const size_t aoff = (size_t)(rowBase + cRow) * K + k0;
        const size_t boff = (size_t)(colBase + cRow) * K + k0;
        #pragma unroll
        for (int c = 0; c < 4; c++) {
            const int ch = cCh0 + c;
            const uint32_t d = base + cRow * (SROW * 2) + ch * 16;
            cp16(d,              Agh + aoff + ch * 8);
            cp16(d + TILE_B,     Agl + aoff + ch * 8);
            cp16(d + 2 * TILE_B, Bgh + boff + ch * 8);
            cp16(d + 3 * TILE_B, Bgl + boff + ch * 8);
        }
        asm volatile("cp.async.commit_group;" ::: "memory");
    };

    float acc[4][4][4] = {};                 // [mt][nt][frag]

    const int nst = K / 64;
    prefetch(0, 0);

    for (int t = 0; t < nst; t++) {
        const bool more = (t + 1 < nst);
        if (more) prefetch(t + 1, (t + 1) & 1);
        if (more) asm volatile("cp.async.wait_group 1;" ::: "memory");
        else      asm volatile("cp.async.wait_group 0;" ::: "memory");
        __syncthreads();

        const uint32_t base = sbase + (t & 1) * STAGE_B;
        const uint32_t uAh = base, uAl = base + TILE_B;
        const uint32_t uBh = base + 2 * TILE_B, uBl = base + 3 * TILE_B;

        #pragma unroll
        for (int kk = 0; kk < 4; kk++) {
            const int kcol = kk * 16;
            uint32_t bh[4][2], bl[4][2];
            #pragma unroll
            for (int nt = 0; nt < 4; nt++) {
                const uint32_t boff =
                    (uint32_t)((nBase + nt * 8 + bRow) * (SROW * 2) +
                               (kcol + bCol8) * 2);
                ldm_x2(uBh + boff, bh[nt]);
                ldm_x2(uBl + boff, bl[nt]);
            }
            #pragma unroll
            for (int mt = 0; mt < 4; mt++) {
                const uint32_t aoff =
                    (uint32_t)((mBase + mt * 16 + aRow) * (SROW * 2) +
                               (kcol + aCol8) * 2);
                uint32_t ah[4], al[4];
                ldm_x4(uAh + aoff, ah);
                ldm_x4(uAl + aoff, al);
                #pragma unroll
                for (int nt = 0; nt < 4; nt++) {
                    mma16816(acc[mt][nt], ah, bh[nt]);
                    mma16816(acc[mt][nt], ah, bl[nt]);
                    mma16816(acc[mt][nt], al, bh[nt]);
                }
            }
        }
        __syncthreads();
    }

    // ---------------- epilogue ----------------
    #pragma unroll
    for (int mt = 0; mt < 4; mt++) {
        #pragma unroll
        for (int nt = 0; nt < 4; nt++) {
            const int r0 = rowBase + mBase + mt * 16 + (lane >> 2);
            const int c0 = colBase + nBase + nt * 8 + 2 * (lane & 3);
            float2 o0, o1;
            o0.x = alpha * acc[mt][nt][0];
            o0.y = alpha * acc[mt][nt][1];
            o1.x = alpha * acc[mt][nt][2];
            o1.y = alpha * acc[mt][nt][3];
            if (HAS_BIAS) {
                const float2 bb = *reinterpret_cast<const float2*>(&bias[c0]);
                o0.x += bb.x; o0.y += bb.y;
                o1.x += bb.x; o1.y += bb.y;
            }
            if (SPLIT_OUT) {
                uint32_t h0, l0, h1, l1;
                split2(o0.x, o0.y, h0, l0);
                split2(o1.x, o1.y, h1, l1);
                *reinterpret_cast<uint32_t*>(&Ch[(size_t)r0 * Nc + c0]) = h0;
                *reinterpret_cast<uint32_t*>(&Cl[(size_t)r0 * Nc + c0]) = l0;
                *reinterpret_cast<uint32_t*>(&Ch[(size_t)(r0 + 8) * Nc + c0]) = h1;
                *reinterpret_cast<uint32_t*>(&Cl[(size_t)(r0 + 8) * Nc + c0]) = l1;
            } else {
                *reinterpret_cast<float2*>(&Cf[(size_t)r0 * Nc + c0]) = o0;
                *reinterpret_cast<float2*>(&Cf[(size_t)(r0 + 8) * Nc + c0]) = o1;
            }
        }
    }
}

// ---------------------------------------------------------------------------
// v[NSEQ,CDIM] fp32 -> vT[CDIM,NSEQ] bf16 hi/lo transpose.
// 32x32 tile; write phase: 512 bf16x2 pairs, 256 threads x 2 pairs, explicit
// flat mapping (pair p -> row p>>4, paircol p&15). All indices in range.
// ---------------------------------------------------------------------------
__global__ void __launch_bounds__(256)
transpose_split_kernel(const float* __restrict__ in,
                       __nv_bfloat16* __restrict__ oh,
                       __nv_bfloat16* __restrict__ ol)
{
    __shared__ float t[32][33];
    const int tid = threadIdx.y * 32 + threadIdx.x;
    const int c = blockIdx.x * 32 + threadIdx.x;     // CDIM index
    const int r = blockIdx.y * 32 + threadIdx.y;     // NSEQ index
    #pragma unroll
    for (int j = 0; j < 32; j += 8)
        t[threadIdx.y + j][threadIdx.x] = in[(size_t)(r + j) * CDIM + c];
    __syncthreads();
    // t[nseq_local][cdim_local]; vT[r2=CDIM][c2=NSEQ], pairs along NSEQ
    #pragma unroll
    for (int i = 0; i < 2; i++) {
        const int p  = tid + i * 256;        // 0..511
        const int rr = p >> 4;               // cdim_local 0..31
        const int pc = p & 15;               // pair index along nseq
        const int r2 = blockIdx.x * 32 + rr;          // CDIM index
        const int c2 = blockIdx.y * 32 + pc * 2;      // NSEQ index (even)
        const float a = t[pc * 2][rr];
        const float b = t[pc * 2 + 1][rr];
        uint32_t h, l;
        split2(a, b, h, l);
        *reinterpret_cast<uint32_t*>(&oh[(size_t)r2 * NSEQ + c2]) = h;
        *reinterpret_cast<uint32_t*>(&ol[(size_t)r2 * NSEQ + c2]) = l;
    }
}

// ---------------------------------------------------------------------------
// Row softmax: read fp32 S row, write bf16 hi/lo probabilities.
// ---------------------------------------------------------------------------
__global__ void __launch_bounds__(256)
softmax_split_kernel(const float* __restrict__ S,
                     __nv_bfloat16* __restrict__ Ph,
                     __nv_bfloat16* __restrict__ Pl)
{
    const int row = blockIdx.x;
    const float4* p = reinterpret_cast<const float4*>(S + (size_t)row * NSEQ);
    uint2* ph = reinterpret_cast<uint2*>(Ph + (size_t)row * NSEQ);
    uint2* pl = reinterpret_cast<uint2*>(Pl + (size_t)row * NSEQ);
    const int tid = threadIdx.x;

    float4 v[8];
    float mx = -INFINITY;
    #pragma unroll
    for (int i = 0; i < 8; i++) {
        v[i] = p[tid + i * 256];
        mx = fmaxf(mx, fmaxf(fmaxf(v[i].x, v[i].y), fmaxf(v[i].z, v[i].w)));
    }

    __shared__ float red[8];
    __shared__ float bcast;
    const int lane = tid & 31, warp = tid >> 5;

    #pragma unroll
    for (int o = 16; o > 0; o >>= 1) mx = fmaxf(mx, __shfl_xor_sync(~0u, mx, o));
    if (lane == 0) red[warp] = mx;
    __syncthreads();
    if (warp == 0) {
        float m = (lane < 8) ? red[lane] : -INFINITY;
        #pragma unroll
        for (int o = 4; o > 0; o >>= 1) m = fmaxf(m, __shfl_xor_sync(~0u, m, o));
        if (lane == 0) bcast = m;
    }
    __syncthreads();
    mx = bcast;
    __syncthreads();

    float sum = 0.f;
    #pragma unroll
    for (int i = 0; i < 8; i++) {
        v[i].x = expf(v[i].x - mx);
        v[i].y = expf(v[i].y - mx);
        v[i].z = expf(v[i].z - mx);
        v[i].w = expf(v[i].w - mx);
        sum += v[i].x + v[i].y + v[i].z + v[i].w;
    }
    #pragma unroll
    for (int o = 16; o > 0; o >>= 1) sum += __shfl_xor_sync(~0u, sum, o);
    if (lane == 0) red[warp] = sum;
    __syncthreads();
    if (warp == 0) {
        float s = (lane < 8) ? red[lane] : 0.f;
        #pragma unroll
        for (int o = 4; o > 0; o >>= 1) s += __shfl_xor_sync(~0u, s, o);
        if (lane == 0) bcast = s;
    }
    __syncthreads();
    const float inv = 1.f / bcast;

    #pragma unroll
    for (int i = 0; i < 8; i++) {
        v[i].x *= inv; v[i].y *= inv; v[i].z *= inv; v[i].w *= inv;
        uint2 h, l;
        split4(v[i], h, l);
        ph[tid + i * 256] = h;
        pl[tid + i * 256] = l;
    }
}

// ---------------------------------------------------------------------------
// Launch
// ---------------------------------------------------------------------------
extern "C" void kernel_launch(void* const* d_in, const int* in_sizes, int n_in,
                              void* d_out, int out_size)
{
    const float* x  = (const float*)d_in[0];
    const float* Wq = (const float*)d_in[1];
    const float* bq = (const float*)d_in[2];
    const float* Wk = (const float*)d_in[3];
    const float* bk = (const float*)d_in[4];
    const float* Wv = (const float*)d_in[5];
    const float* bv = (const float*)d_in[6];
    const float* Wo = (const float*)d_in[7];
    const float* bo = (const float*)d_in[8];
    float* out = (float*)d_out;

    __nv_bfloat16 *xh, *xl, *Wqh, *Wql, *Wkh, *Wkl, *Wvh, *Wvl, *Woh, *Wol;
    __nv_bfloat16 *qh, *ql, *kh, *kl, *vTh, *vTl, *sh, *sl, *avh, *avl;
    float *v, *s;
    cudaGetSymbolAddress((void**)&xh,  g_xh);  cudaGetSymbolAddress((void**)&xl,  g_xl);
    cudaGetSymbolAddress((void**)&Wqh, g_Wqh); cudaGetSymbolAddress((void**)&Wql, g_Wql);
    cudaGetSymbolAddress((void**)&Wkh, g_Wkh); cudaGetSymbolAddress((void**)&Wkl, g_Wkl);
    cudaGetSymbolAddress((void**)&Wvh, g_Wvh); cudaGetSymbolAddress((void**)&Wvl, g_Wvl);
    cudaGetSymbolAddress((void**)&Woh, g_Woh); cudaGetSymbolAddress((void**)&Wol, g_Wol);
    cudaGetSymbolAddress((void**)&qh,  g_qh);  cudaGetSymbolAddress((void**)&ql,  g_ql);
    cudaGetSymbolAddress((void**)&kh,  g_kh);  cudaGetSymbolAddress((void**)&kl,  g_kl);
    cudaGetSymbolAddress((void**)&v,   g_v);
    cudaGetSymbolAddress((void**)&vTh, g_vTh); cudaGetSymbolAddress((void**)&vTl, g_vTl);
    cudaGetSymbolAddress((void**)&s,   g_s);
    cudaGetSymbolAddress((void**)&sh,  g_sh);  cudaGetSymbolAddress((void**)&sl,  g_sl);
    cudaGetSymbolAddress((void**)&avh, g_avh); cudaGetSymbolAddress((void**)&avl, g_avl);

    cudaFuncSetAttribute(hmma_gemm<true, false>,
                         cudaFuncAttributeMaxDynamicSharedMemorySize, SMEM_SZ);
    cudaFuncSetAttribute(hmma_gemm<true, true>,
                         cudaFuncAttributeMaxDynamicSharedMemorySize, SMEM_SZ);
    cudaFuncSetAttribute(hmma_gemm<false, false>,
                         cudaFuncAttributeMaxDynamicSharedMemorySize, SMEM_SZ);
    cudaFuncSetAttribute(hmma_gemm<false, true>,
                         cudaFuncAttributeMaxDynamicSharedMemorySize, SMEM_SZ);

    const float scale = 1.0f / sqrtf((float)HDIM);
    const dim3 blk(256);

    // ---- pre-split inputs ----
    split_kernel<<<(NSEQ * CDIM / 4 + 255) / 256, blk>>>(x,  xh,  xl,  NSEQ * CDIM / 4);
    split_kernel<<<(HDIM * CDIM / 4 + 255) / 256, blk>>>(Wq, Wqh, Wql, HDIM * CDIM / 4);
    split_kernel<<<(HDIM * CDIM / 4 + 255) / 256, blk>>>(Wk, Wkh, Wkl, HDIM * CDIM / 4);
    split_kernel<<<(CDIM * CDIM / 4 + 255) / 256, blk>>>(Wv, Wvh, Wvl, CDIM * CDIM / 4);
    split_kernel<<<(CDIM * CDIM / 4 + 255) / 256, blk>>>(Wo, Woh, Wol, CDIM * CDIM / 4);

    // ---- q, k (split out), v (fp32 out) ----
    hmma_gemm<true, true><<<dim3(HDIM / 128, NSEQ / 128), blk, SMEM_SZ>>>(
        xh, xl, Wqh, Wql, bq, nullptr, qh, ql, NSEQ, HDIM, CDIM, 1.0f);
    hmma_gemm<true, true><<<dim3(HDIM / 128, NSEQ / 128), blk, SMEM_SZ>>>(
        xh, xl, Wkh, Wkl, bk, nullptr, kh, kl, NSEQ, HDIM, CDIM, 1.0f);
    hmma_gemm<true, false><<<dim3(CDIM / 128, NSEQ / 128), blk, SMEM_SZ>>>(
        xh, xl, Wvh, Wvl, bv, v, nullptr, nullptr, NSEQ, CDIM, CDIM, 1.0f);

    // ---- vT (split) ----
    transpose_split_kernel<<<dim3(CDIM / 32, NSEQ / 32), dim3(32, 8)>>>(v, vTh, vTl);

    // ---- S = scale * q @ k^T (fp32) ----
    hmma_gemm<false, false><<<dim3(NSEQ / 128, NSEQ / 128), blk, SMEM_SZ>>>(
        qh, ql, kh, kl, nullptr, s, nullptr, nullptr, NSEQ, NSEQ, HDIM, scale);

    // ---- softmax -> split probs ----
    softmax_split_kernel<<<NSEQ, blk>>>(s, sh, sl);

    // ---- av = P @ vT^T (split out) ----
    hmma_gemm<false, true><<<dim3(CDIM / 128, NSEQ / 128), blk, SMEM_SZ>>>(
        sh, sl, vTh, vTl, nullptr, nullptr, avh, avl, NSEQ, CDIM, NSEQ, 1.0f);

    // ---- out = av @ Wo^T + bo (fp32) ----
    hmma_gemm<true, false><<<dim3(CDIM / 128, NSEQ / 128), blk, SMEM_SZ>>>(
        avh, avl, Woh, Wol, bo, out, nullptr, nullptr, NSEQ, CDIM, CDIM, 1.0f);
}

// round 12
// speedup vs baseline: 2.4245x; 1.2106x over previous
#include <cuda_runtime.h>
#include <cuda_bf16.h>
#include <math.h>
#include <stdint.h>

#define NSEQ 8192
#define CDIM 1024
#define HDIM 128

// ---------------------------------------------------------------------------
// Scratch (__device__ globals; no cudaMalloc allowed)
// ---------------------------------------------------------------------------
__device__ __align__(256) __nv_bfloat16 g_xh [NSEQ * CDIM];
__device__ __align__(256) __nv_bfloat16 g_xl [NSEQ * CDIM];
__device__ __align__(256) __nv_bfloat16 g_Wqh[HDIM * CDIM];
__device__ __align__(256) __nv_bfloat16 g_Wql[HDIM * CDIM];
__device__ __align__(256) __nv_bfloat16 g_Wkh[HDIM * CDIM];
__device__ __align__(256) __nv_bfloat16 g_Wkl[HDIM * CDIM];
__device__ __align__(256) __nv_bfloat16 g_Wvh[CDIM * CDIM];
__device__ __align__(256) __nv_bfloat16 g_Wvl[CDIM * CDIM];
__device__ __align__(256) __nv_bfloat16 g_Woh[CDIM * CDIM];
__device__ __align__(256) __nv_bfloat16 g_Wol[CDIM * CDIM];
__device__ __align__(256) __nv_bfloat16 g_qh [NSEQ * HDIM];
__device__ __align__(256) __nv_bfloat16 g_ql [NSEQ * HDIM];
__device__ __align__(256) __nv_bfloat16 g_kh [NSEQ * HDIM];
__device__ __align__(256) __nv_bfloat16 g_kl [NSEQ * HDIM];
__device__ __align__(256) float         g_v  [NSEQ * CDIM];            // 32 MB
__device__ __align__(256) __nv_bfloat16 g_vTh[CDIM * NSEQ];
__device__ __align__(256) __nv_bfloat16 g_vTl[CDIM * NSEQ];
__device__ __align__(256) float         g_s  [(size_t)NSEQ * NSEQ];    // 256 MB
__device__ __align__(256) __nv_bfloat16 g_sh [(size_t)NSEQ * NSEQ];    // 128 MB
__device__ __align__(256) __nv_bfloat16 g_sl [(size_t)NSEQ * NSEQ];    // 128 MB
__device__ __align__(256) __nv_bfloat16 g_avh[NSEQ * CDIM];
__device__ __align__(256) __nv_bfloat16 g_avl[NSEQ * CDIM];

// ---------------------------------------------------------------------------
// Helpers (baseline PTX only; assembles for plain sm_103)
// ---------------------------------------------------------------------------
__device__ __forceinline__ uint32_t smem_u32(const void* p) {
    uint32_t a;
    asm("{ .reg .u64 t; cvta.to.shared.u64 t, %1; cvt.u32.u64 %0, t; }"
        : "=r"(a) : "l"(p));
    return a;
}
__device__ __forceinline__ void ldm_x4(uint32_t addr, uint32_t* r) {
    asm volatile("ldmatrix.sync.aligned.m8n8.x4.shared.b16 {%0,%1,%2,%3}, [%4];"
        : "=r"(r[0]), "=r"(r[1]), "=r"(r[2]), "=r"(r[3]) : "r"(addr));
}
__device__ __forceinline__ void mma16816(float* c, const uint32_t* a, const uint32_t* b) {
    asm volatile("mma.sync.aligned.m16n8k16.row.col.f32.bf16.bf16.f32 "
        "{%0,%1,%2,%3}, {%4,%5,%6,%7}, {%8,%9}, {%0,%1,%2,%3};"
        : "+f"(c[0]), "+f"(c[1]), "+f"(c[2]), "+f"(c[3])
        : "r"(a[0]), "r"(a[1]), "r"(a[2]), "r"(a[3]), "r"(b[0]), "r"(b[1]));
}
__device__ __forceinline__ void cp16(uint32_t dst, const void* src) {
    asm volatile("cp.async.cg.shared.global [%0], [%1], 16;"
        :: "r"(dst), "l"(src) : "memory");
}

// fp32 -> (hi bf16 truncated, lo bf16 rounded) split, packed bf16x2
__device__ __forceinline__ void split4(const float4 v, uint2& hi, uint2& lo) {
    uint32_t bx = __float_as_uint(v.x), by = __float_as_uint(v.y);
    uint32_t bz = __float_as_uint(v.z), bw = __float_as_uint(v.w);
    hi.x = (bx >> 16) | (by & 0xFFFF0000u);
    hi.y = (bz >> 16) | (bw & 0xFFFF0000u);
    float lx = v.x - __uint_as_float(bx & 0xFFFF0000u);
    float ly = v.y - __uint_as_float(by & 0xFFFF0000u);
    float lz = v.z - __uint_as_float(bz & 0xFFFF0000u);
    float lw = v.w - __uint_as_float(bw & 0xFFFF0000u);
    asm("cvt.rn.bf16x2.f32 %0, %1, %2;" : "=r"(lo.x) : "f"(ly), "f"(lx));
    asm("cvt.rn.bf16x2.f32 %0, %1, %2;" : "=r"(lo.y) : "f"(lw), "f"(lz));
}
__device__ __forceinline__ void split2(float a, float b, uint32_t& hi, uint32_t& lo) {
    uint32_t ba = __float_as_uint(a), bb = __float_as_uint(b);
    hi = (ba >> 16) | (bb & 0xFFFF0000u);
    float la = a - __uint_as_float(ba & 0xFFFF0000u);
    float lb = b - __uint_as_float(bb & 0xFFFF0000u);
    asm("cvt.rn.bf16x2.f32 %0, %1, %2;" : "=r"(lo) : "f"(lb), "f"(la));
}

// ---------------------------------------------------------------------------
// Elementwise fp32 -> bf16 hi/lo split
// ---------------------------------------------------------------------------
__global__ void __launch_bounds__(256)
split_kernel(const float* __restrict__ in, __nv_bfloat16* __restrict__ oh,
             __nv_bfloat16* __restrict__ ol, int n4)
{
    const int i = blockIdx.x * 256 + threadIdx.x;
    if (i >= n4) return;
    float4 v = reinterpret_cast<const float4*>(in)[i];
    uint2 h, l;
    split4(v, h, l);
    reinterpret_cast<uint2*>(oh)[i] = h;
    reinterpret_cast<uint2*>(ol)[i] = l;
}

// ---------------------------------------------------------------------------
// Split-bf16 HMMA GEMM, cp.async double-buffered, 2 CTAs/SM.
//   C = alpha * A[M,K] @ B[Nc,K]^T (+bias)
// CTA 128x128, BK=32, 256 threads, warps 2x4 (warp tile 64x32), 3 MMA passes.
// SROW=40 (32+8 pad): ldmatrix 8-row fetch hits 8 distinct banks.
// ---------------------------------------------------------------------------
#define SROW    40                         // bf16 per smem row (32 + 8 pad)
#define TILE_B  (128 * SROW * 2)           // 10240 B
#define STAGE_B (4 * TILE_B)               // Ah, Al, Bh, Bl = 40960 B
#define SMEM_SZ (2 * STAGE_B)              // double buffer = 81920 B

template <bool HAS_BIAS, bool SPLIT_OUT>
__global__ void __launch_bounds__(256, 2)
hmma_gemm(const __nv_bfloat16* __restrict__ Agh, const __nv_bfloat16* __restrict__ Agl,
          const __nv_bfloat16* __restrict__ Bgh, const __nv_bfloat16* __restrict__ Bgl,
          const float* __restrict__ bias,
          float* __restrict__ Cf,
          __nv_bfloat16* __restrict__ Ch, __nv_bfloat16* __restrict__ Cl,
          int M, int Nc, int K, float alpha)
{
    extern __shared__ __align__(256) char smem[];
    const uint32_t sbase = smem_u32(smem);

    const int tid  = threadIdx.x;
    const int warp = tid >> 5;
    const int lane = tid & 31;
    const int warp_m = warp >> 2;            // 0..1
    const int warp_n = warp & 3;             // 0..3
    const int mBase  = warp_m * 64;
    const int nBase  = warp_n * 32;

    const int rowBase = blockIdx.y * 128;
    const int colBase = blockIdx.x * 128;

    // ldmatrix per-lane offsets
    const int aRow  = (lane & 15);
    const int aCol8 = 8 * (lane >> 4);
    // B x4: lane group g = lane>>3: matrices {nt0:k0-7, nt0:k8-15, nt1:k0-7, nt1:k8-15}
    const int bg    = lane >> 3;             // 0..3
    const int bRow  = (lane & 7) + 8 * (bg >> 1);   // n-offset within pair (0..15)
    const int bCol8 = 8 * (bg & 1);                 // k-offset 0 or 8

    // cp.async mapping: per tile 128 rows x 4 chunks of 16B (row = 64 B data)
    const int cRow = tid >> 1;               // 0..127 (2 threads per row)
    const int cCh0 = (tid & 1) * 2;          // chunks 0-1 or 2-3

    auto prefetch = [&](int t, int buf) {
        const uint32_t base = sbase + buf * STAGE_B;
        const int k0 = t * 32;
        const size_t aoff = (size_t)(rowBase + cRow) * K + k0;
        const size_t boff = (size_t)(colBase + cRow) * K + k0;
        #pragma unroll
        for (int c = 0; c < 2; c++) {
            const int ch = cCh0 + c;
            const uint32_t d = base + cRow * (SROW * 2) + ch * 16;
            cp16(d,              Agh + aoff + ch * 8);
            cp16(d + TILE_B,     Agl + aoff + ch * 8);
            cp16(d + 2 * TILE_B, Bgh + boff + ch * 8);
            cp16(d + 3 * TILE_B, Bgl + boff + ch * 8);
        }
        asm volatile("cp.async.commit_group;" ::: "memory");
    };

    float acc[4][4][4] = {};                 // [mt][nt][frag]

    const int nst = K / 32;
    prefetch(0, 0);

    for (int t = 0; t < nst; t++) {
        const bool more = (t + 1 < nst);
        if (more) prefetch(t + 1, (t + 1) & 1);
        if (more) asm volatile("cp.async.wait_group 1;" ::: "memory");
        else      asm volatile("cp.async.wait_group 0;" ::: "memory");
        __syncthreads();

        const uint32_t base = sbase + (t & 1) * STAGE_B;
        const uint32_t uAh = base, uAl = base + TILE_B;
        const uint32_t uBh = base + 2 * TILE_B, uBl = base + 3 * TILE_B;

        #pragma unroll
        for (int kk = 0; kk < 2; kk++) {
            const int kcol = kk * 16;
            // B fragments: 2 ldm_x4 each for hi/lo cover all 4 n-tiles
            uint32_t bh[4][2], bl[4][2];
            #pragma unroll
            for (int np = 0; np < 2; np++) {
                const uint32_t boff =
                    (uint32_t)((nBase + np * 16 + bRow) * (SROW * 2) +
                               (kcol + bCol8) * 2);
                uint32_t r4[4];
                ldm_x4(uBh + boff, r4);
                bh[np * 2][0] = r4[0]; bh[np * 2][1] = r4[1];
                bh[np * 2 + 1][0] = r4[2]; bh[np * 2 + 1][1] = r4[3];
                ldm_x4(uBl + boff, r4);
                bl[np * 2][0] = r4[0]; bl[np * 2][1] = r4[1];
                bl[np * 2 + 1][0] = r4[2]; bl[np * 2 + 1][1] = r4[3];
            }
            #pragma unroll
            for (int mt = 0; mt < 4; mt++) {
                const uint32_t aoff =
                    (uint32_t)((mBase + mt * 16 + aRow) * (SROW * 2) +
                               (kcol + aCol8) * 2);
                uint32_t ah[4], al[4];
                ldm_x4(uAh + aoff, ah);
                ldm_x4(uAl + aoff, al);
                #pragma unroll
                for (int nt = 0; nt < 4; nt++) {
                    mma16816(acc[mt][nt], ah, bh[nt]);
                    mma16816(acc[mt][nt], ah, bl[nt]);
                    mma16816(acc[mt][nt], al, bh[nt]);
                }
            }
        }
        __syncthreads();
    }

    // ---------------- epilogue ----------------
    #pragma unroll
    for (int mt = 0; mt < 4; mt++) {
        #pragma unroll
        for (int nt = 0; nt < 4; nt++) {
            const int r0 = rowBase + mBase + mt * 16 + (lane >> 2);
            const int c0 = colBase + nBase + nt * 8 + 2 * (lane & 3);
            float2 o0, o1;
            o0.x = alpha * acc[mt][nt][0];
            o0.y = alpha * acc[mt][nt][1];
            o1.x = alpha * acc[mt][nt][2];
            o1.y = alpha * acc[mt][nt][3];
            if (HAS_BIAS) {
                const float2 bb = *reinterpret_cast<const float2*>(&bias[c0]);
                o0.x += bb.x; o0.y += bb.y;
                o1.x += bb.x; o1.y += bb.y;
            }
            if (SPLIT_OUT) {
                uint32_t h0, l0, h1, l1;
                split2(o0.x, o0.y, h0, l0);
                split2(o1.x, o1.y, h1, l1);
                *reinterpret_cast<uint32_t*>(&Ch[(size_t)r0 * Nc + c0]) = h0;
                *reinterpret_cast<uint32_t*>(&Cl[(size_t)r0 * Nc + c0]) = l0;
                *reinterpret_cast<uint32_t*>(&Ch[(size_t)(r0 + 8) * Nc + c0]) = h1;
                *reinterpret_cast<uint32_t*>(&Cl[(size_t)(r0 + 8) * Nc + c0]) = l1;
            } else {
                *reinterpret_cast<float2*>(&Cf[(size_t)r0 * Nc + c0]) = o0;
                *reinterpret_cast<float2*>(&Cf[(size_t)(r0 + 8) * Nc + c0]) = o1;
            }
        }
    }
}

// ---------------------------------------------------------------------------
// v[NSEQ,CDIM] fp32 -> vT[CDIM,NSEQ] bf16 hi/lo transpose (explicit mapping)
// ---------------------------------------------------------------------------
__global__ void __launch_bounds__(256)
transpose_split_kernel(const float* __restrict__ in,
                       __nv_bfloat16* __restrict__ oh,
                       __nv_bfloat16* __restrict__ ol)
{
    __shared__ float t[32][33];
    const int tid = threadIdx.y * 32 + threadIdx.x;
    const int c = blockIdx.x * 32 + threadIdx.x;     // CDIM index
    const int r = blockIdx.y * 32 + threadIdx.y;     // NSEQ index
    #pragma unroll
    for (int j = 0; j < 32; j += 8)
        t[threadIdx.y + j][threadIdx.x] = in[(size_t)(r + j) * CDIM + c];
    __syncthreads();
    #pragma unroll
    for (int i = 0; i < 2; i++) {
        const int p  = tid + i * 256;        // 0..511
        const int rr = p >> 4;               // cdim_local 0..31
        const int pc = p & 15;               // pair index along nseq
        const int r2 = blockIdx.x * 32 + rr;          // CDIM index
        const int c2 = blockIdx.y * 32 + pc * 2;      // NSEQ index (even)
        const float a = t[pc * 2][rr];
        const float b = t[pc * 2 + 1][rr];
        uint32_t h, l;
        split2(a, b, h, l);
        *reinterpret_cast<uint32_t*>(&oh[(size_t)r2 * NSEQ + c2]) = h;
        *reinterpret_cast<uint32_t*>(&ol[(size_t)r2 * NSEQ + c2]) = l;
    }
}

// ---------------------------------------------------------------------------
// Row softmax: read fp32 S row, write bf16 hi/lo probabilities.
// ---------------------------------------------------------------------------
__global__ void __launch_bounds__(256)
softmax_split_kernel(const float* __restrict__ S,
                     __nv_bfloat16* __restrict__ Ph,
                     __nv_bfloat16* __restrict__ Pl)
{
    const int row = blockIdx.x;
    const float4* p = reinterpret_cast<const float4*>(S + (size_t)row * NSEQ);
    uint2* ph = reinterpret_cast<uint2*>(Ph + (size_t)row * NSEQ);
    uint2* pl = reinterpret_cast<uint2*>(Pl + (size_t)row * NSEQ);
    const int tid = threadIdx.x;

    float4 v[8];
    float mx = -INFINITY;
    #pragma unroll
    for (int i = 0; i < 8; i++) {
        v[i] = p[tid + i * 256];
        mx = fmaxf(mx, fmaxf(fmaxf(v[i].x, v[i].y), fmaxf(v[i].z, v[i].w)));
    }

    __shared__ float red[8];
    __shared__ float bcast;
    const int lane = tid & 31, warp = tid >> 5;

    #pragma unroll
    for (int o = 16; o > 0; o >>= 1) mx = fmaxf(mx, __shfl_xor_sync(~0u, mx, o));
    if (lane == 0) red[warp] = mx;
    __syncthreads();
    if (warp == 0) {
        float m = (lane < 8) ? red[lane] : -INFINITY;
        #pragma unroll
        for (int o = 4; o > 0; o >>= 1) m = fmaxf(m, __shfl_xor_sync(~0u, m, o));
        if (lane == 0) bcast = m;
    }
    __syncthreads();
    mx = bcast;
    __syncthreads();

    float sum = 0.f;
    #pragma unroll
    for (int i = 0; i < 8; i++) {
        v[i].x = expf(v[i].x - mx);
        v[i].y = expf(v[i].y - mx);
        v[i].z = expf(v[i].z - mx);
        v[i].w = expf(v[i].w - mx);
        sum += v[i].x + v[i].y + v[i].z + v[i].w;
    }
    #pragma unroll
    for (int o = 16; o > 0; o >>= 1) sum += __shfl_xor_sync(~0u, sum, o);
    if (lane == 0) red[warp] = sum;
    __syncthreads();
    if (warp == 0) {
        float s = (lane < 8) ? red[lane] : 0.f;
        #pragma unroll
        for (int o = 4; o > 0; o >>= 1) s += __shfl_xor_sync(~0u, s, o);
        if (lane == 0) bcast = s;
    }
    __syncthreads();
    const float inv = 1.f / bcast;

    #pragma unroll
    for (int i = 0; i < 8; i++) {
        v[i].x *= inv; v[i].y *= inv; v[i].z *= inv; v[i].w *= inv;
        uint2 h, l;
        split4(v[i], h, l);
        ph[tid + i * 256] = h;
        pl[tid + i * 256] = l;
    }
}

// ---------------------------------------------------------------------------
// Launch
// ---------------------------------------------------------------------------
extern "C" void kernel_launch(void* const* d_in, const int* in_sizes, int n_in,
                              void* d_out, int out_size)
{
    const float* x  = (const float*)d_in[0];
    const float* Wq = (const float*)d_in[1];
    const float* bq = (const float*)d_in[2];
    const float* Wk = (const float*)d_in[3];
    const float* bk = (const float*)d_in[4];
    const float* Wv = (const float*)d_in[5];
    const float* bv = (const float*)d_in[6];
    const float* Wo = (const float*)d_in[7];
    const float* bo = (const float*)d_in[8];
    float* out = (float*)d_out;

    __nv_bfloat16 *xh, *xl, *Wqh, *Wql, *Wkh, *Wkl, *Wvh, *Wvl, *Woh, *Wol;
    __nv_bfloat16 *qh, *ql, *kh, *kl, *vTh, *vTl, *sh, *sl, *avh, *avl;
    float *v, *s;
    cudaGetSymbolAddress((void**)&xh,  g_xh);  cudaGetSymbolAddress((void**)&xl,  g_xl);
    cudaGetSymbolAddress((void**)&Wqh, g_Wqh); cudaGetSymbolAddress((void**)&Wql, g_Wql);
    cudaGetSymbolAddress((void**)&Wkh, g_Wkh); cudaGetSymbolAddress((void**)&Wkl, g_Wkl);
    cudaGetSymbolAddress((void**)&Wvh, g_Wvh); cudaGetSymbolAddress((void**)&Wvl, g_Wvl);
    cudaGetSymbolAddress((void**)&Woh, g_Woh); cudaGetSymbolAddress((void**)&Wol, g_Wol);
    cudaGetSymbolAddress((void**)&qh,  g_qh);  cudaGetSymbolAddress((void**)&ql,  g_ql);
    cudaGetSymbolAddress((void**)&kh,  g_kh);  cudaGetSymbolAddress((void**)&kl,  g_kl);
    cudaGetSymbolAddress((void**)&v,   g_v);
    cudaGetSymbolAddress((void**)&vTh, g_vTh); cudaGetSymbolAddress((void**)&vTl, g_vTl);
    cudaGetSymbolAddress((void**)&s,   g_s);
    cudaGetSymbolAddress((void**)&sh,  g_sh);  cudaGetSymbolAddress((void**)&sl,  g_sl);
    cudaGetSymbolAddress((void**)&avh, g_avh); cudaGetSymbolAddress((void**)&avl, g_avl);

    cudaFuncSetAttribute(hmma_gemm<true, false>,
                         cudaFuncAttributeMaxDynamicSharedMemorySize, SMEM_SZ);
    cudaFuncSetAttribute(hmma_gemm<true, true>,
                         cudaFuncAttributeMaxDynamicSharedMemorySize, SMEM_SZ);
    cudaFuncSetAttribute(hmma_gemm<false, false>,
                         cudaFuncAttributeMaxDynamicSharedMemorySize, SMEM_SZ);
    cudaFuncSetAttribute(hmma_gemm<false, true>,
                         cudaFuncAttributeMaxDynamicSharedMemorySize, SMEM_SZ);

    const float scale = 1.0f / sqrtf((float)HDIM);
    const dim3 blk(256);

    // ---- pre-split inputs ----
    split_kernel<<<(NSEQ * CDIM / 4 + 255) / 256, blk>>>(x,  xh,  xl,  NSEQ * CDIM / 4);
    split_kernel<<<(HDIM * CDIM / 4 + 255) / 256, blk>>>(Wq, Wqh, Wql, HDIM * CDIM / 4);
    split_kernel<<<(HDIM * CDIM / 4 + 255) / 256, blk>>>(Wk, Wkh, Wkl, HDIM * CDIM / 4);
    split_kernel<<<(CDIM * CDIM / 4 + 255) / 256, blk>>>(Wv, Wvh, Wvl, CDIM * CDIM / 4);
    split_kernel<<<(CDIM * CDIM / 4 + 255) / 256, blk>>>(Wo, Woh, Wol, CDIM * CDIM / 4);

    // ---- q, k (split out), v (fp32 out) ----
    hmma_gemm<true, true><<<dim3(HDIM / 128, NSEQ / 128), blk, SMEM_SZ>>>(
        xh, xl, Wqh, Wql, bq, nullptr, qh, ql, NSEQ, HDIM, CDIM, 1.0f);
    hmma_gemm<true, true><<<dim3(HDIM / 128, NSEQ / 128), blk, SMEM_SZ>>>(
        xh, xl, Wkh, Wkl, bk, nullptr, kh, kl, NSEQ, HDIM, CDIM, 1.0f);
    hmma_gemm<true, false><<<dim3(CDIM / 128, NSEQ / 128), blk, SMEM_SZ>>>(
        xh, xl, Wvh, Wvl, bv, v, nullptr, nullptr, NSEQ, CDIM, CDIM, 1.0f);

    // ---- vT (split) ----
    transpose_split_kernel<<<dim3(CDIM / 32, NSEQ / 32), dim3(32, 8)>>>(v, vTh, vTl);

    // ---- S = scale * q @ k^T (fp32) ----
    hmma_gemm<false, false><<<dim3(NSEQ / 128, NSEQ / 128), blk, SMEM_SZ>>>(
        qh, ql, kh, kl, nullptr, s, nullptr, nullptr, NSEQ, NSEQ, HDIM, scale);

    // ---- softmax -> split probs ----
    softmax_split_kernel<<<NSEQ, blk>>>(s, sh, sl);

    // ---- av = P @ vT^T (split out) ----
    hmma_gemm<false, true><<<dim3(CDIM / 128, NSEQ / 128), blk, SMEM_SZ>>>(
        sh, sl, vTh, vTl, nullptr, nullptr, avh, avl, NSEQ, CDIM, NSEQ, 1.0f);

    // ---- out = av @ Wo^T + bo (fp32) ----
    hmma_gemm<true, false><<<dim3(CDIM / 128, NSEQ / 128), blk, SMEM_SZ>>>(
        avh, avl, Woh, Wol, bo, out, nullptr, nullptr, NSEQ, CDIM, CDIM, 1.0f);
}

// round 13
// speedup vs baseline: 3.1789x; 1.3112x over previous
#include <cuda_runtime.h>
#include <cuda_fp16.h>
#include <math.h>
#include <stdint.h>

#define NSEQ 8192
#define CDIM 1024
#define HDIM 128

// ---------------------------------------------------------------------------
// Scratch (__device__ globals; no cudaMalloc allowed). fp16 hi/lo operands.
// ---------------------------------------------------------------------------
__device__ __align__(256) __half g_xh [NSEQ * CDIM];
__device__ __align__(256) __half g_xl [NSEQ * CDIM];
__device__ __align__(256) __half g_Wqh[HDIM * CDIM];
__device__ __align__(256) __half g_Wql[HDIM * CDIM];
__device__ __align__(256) __half g_Wkh[HDIM * CDIM];
__device__ __align__(256) __half g_Wkl[HDIM * CDIM];
__device__ __align__(256) __half g_Wvh[CDIM * CDIM];
__device__ __align__(256) __half g_Wvl[CDIM * CDIM];
__device__ __align__(256) __half g_Woh[CDIM * CDIM];
__device__ __align__(256) __half g_Wol[CDIM * CDIM];
__device__ __align__(256) __half g_qh [NSEQ * HDIM];
__device__ __align__(256) __half g_ql [NSEQ * HDIM];
__device__ __align__(256) __half g_kh [NSEQ * HDIM];
__device__ __align__(256) __half g_kl [NSEQ * HDIM];
__device__ __align__(256) float  g_v  [NSEQ * CDIM];            // 32 MB
__device__ __align__(256) __half g_vTh[CDIM * NSEQ];
__device__ __align__(256) __half g_vTl[CDIM * NSEQ];
__device__ __align__(256) float  g_s  [(size_t)NSEQ * NSEQ];    // 256 MB
__device__ __align__(256) __half g_sh [(size_t)NSEQ * NSEQ];    // 128 MB
__device__ __align__(256) __half g_sl [(size_t)NSEQ * NSEQ];    // 128 MB
__device__ __align__(256) __half g_avh[NSEQ * CDIM];
__device__ __align__(256) __half g_avl[NSEQ * CDIM];

// ---------------------------------------------------------------------------
// Helpers (baseline PTX only; assembles for plain sm_103)
// ---------------------------------------------------------------------------
__device__ __forceinline__ uint32_t smem_u32(const void* p) {
    uint32_t a;
    asm("{ .reg .u64 t; cvta.to.shared.u64 t, %1; cvt.u32.u64 %0, t; }"
        : "=r"(a) : "l"(p));
    return a;
}
__device__ __forceinline__ void ldm_x4(uint32_t addr, uint32_t* r) {
    asm volatile("ldmatrix.sync.aligned.m8n8.x4.shared.b16 {%0,%1,%2,%3}, [%4];"
        : "=r"(r[0]), "=r"(r[1]), "=r"(r[2]), "=r"(r[3]) : "r"(addr));
}
__device__ __forceinline__ void mma16816(float* c, const uint32_t* a, const uint32_t* b) {
    asm volatile("mma.sync.aligned.m16n8k16.row.col.f32.f16.f16.f32 "
        "{%0,%1,%2,%3}, {%4,%5,%6,%7}, {%8,%9}, {%0,%1,%2,%3};"
        : "+f"(c[0]), "+f"(c[1]), "+f"(c[2]), "+f"(c[3])
        : "r"(a[0]), "r"(a[1]), "r"(a[2]), "r"(a[3]), "r"(b[0]), "r"(b[1]));
}
__device__ __forceinline__ void cp16(uint32_t dst, const void* src) {
    asm volatile("cp.async.cg.shared.global [%0], [%1], 16;"
        :: "r"(dst), "l"(src) : "memory");
}

// fp32 -> (hi fp16 rn, lo fp16 of exact residual), packed f16x2.
// PTX cvt f16x2: first source -> HIGH half, second -> LOW half.
__device__ __forceinline__ void split2(float a, float b, uint32_t& hi, uint32_t& lo) {
    asm("cvt.rn.f16x2.f32 %0, %1, %2;" : "=r"(hi) : "f"(b), "f"(a));
    __half2 h2 = *reinterpret_cast<__half2*>(&hi);
    float la = a - __low2float(h2);
    float lb = b - __high2float(h2);
    asm("cvt.rn.f16x2.f32 %0, %1, %2;" : "=r"(lo) : "f"(lb), "f"(la));
}
__device__ __forceinline__ void split4(const float4 v, uint2& hi, uint2& lo) {
    split2(v.x, v.y, hi.x, lo.x);
    split2(v.z, v.w, hi.y, lo.y);
}

// ---------------------------------------------------------------------------
// Elementwise fp32 -> fp16 hi/lo split
// ---------------------------------------------------------------------------
__global__ void __launch_bounds__(256)
split_kernel(const float* __restrict__ in, __half* __restrict__ oh,
             __half* __restrict__ ol, int n4)
{
    const int i = blockIdx.x * 256 + threadIdx.x;
    if (i >= n4) return;
    float4 v = reinterpret_cast<const float4*>(in)[i];
    uint2 h, l;
    split4(v, h, l);
    reinterpret_cast<uint2*>(oh)[i] = h;
    reinterpret_cast<uint2*>(ol)[i] = l;
}

// ---------------------------------------------------------------------------
// Split-fp16 HMMA GEMM, cp.async double-buffered, 2 CTAs/SM.
//   C = alpha * A[M,K] @ B[Nc,K]^T (+bias)
// CTA 128x128, BK=32, 256 threads, warps 2x4 (warp tile 64x32).
// Passes: AhBh + AlBh (+ AhBl unless DROP_BL). SROW=40 keeps ldmatrix
// conflict-free.
// ---------------------------------------------------------------------------
#define SROW    40                         // fp16 per smem row (32 + 8 pad)
#define TILE_B  (128 * SROW * 2)           // 10240 B
#define STAGE_B (4 * TILE_B)               // Ah, Al, Bh, Bl = 40960 B
#define SMEM_SZ (2 * STAGE_B)              // double buffer = 81920 B

template <bool HAS_BIAS, bool SPLIT_OUT, bool DROP_BL>
__global__ void __launch_bounds__(256, 2)
hmma_gemm(const __half* __restrict__ Agh, const __half* __restrict__ Agl,
          const __half* __restrict__ Bgh, const __half* __restrict__ Bgl,
          const float* __restrict__ bias,
          float* __restrict__ Cf,
          __half* __restrict__ Ch, __half* __restrict__ Cl,
          int M, int Nc, int K, float alpha)
{
    extern __shared__ __align__(256) char smem[];
    const uint32_t sbase = smem_u32(smem);

    const int tid  = threadIdx.x;
    const int warp = tid >> 5;
    const int lane = tid & 31;
    const int warp_m = warp >> 2;            // 0..1
    const int warp_n = warp & 3;             // 0..3
    const int mBase  = warp_m * 64;
    const int nBase  = warp_n * 32;

    const int rowBase = blockIdx.y * 128;
    const int colBase = blockIdx.x * 128;

    // ldmatrix per-lane offsets
    const int aRow  = (lane & 15);
    const int aCol8 = 8 * (lane >> 4);
    const int bg    = lane >> 3;             // 0..3
    const int bRow  = (lane & 7) + 8 * (bg >> 1);
    const int bCol8 = 8 * (bg & 1);

    // cp.async mapping: per tile 128 rows x 4 chunks of 16B
    const int cRow = tid >> 1;               // 0..127
    const int cCh0 = (tid & 1) * 2;          // chunks 0-1 or 2-3

    auto prefetch = [&](int t, int buf) {
        const uint32_t base = sbase + buf * STAGE_B;
        const int k0 = t * 32;
        const size_t aoff = (size_t)(rowBase + cRow) * K + k0;
        const size_t boff = (size_t)(colBase + cRow) * K + k0;
        #pragma unroll
        for (int c = 0; c < 2; c++) {
            const int ch = cCh0 + c;
            const uint32_t d = base + cRow * (SROW * 2) + ch * 16;
            cp16(d,              Agh + aoff + ch * 8);
            cp16(d + TILE_B,     Agl + aoff + ch * 8);
            cp16(d + 2 * TILE_B, Bgh + boff + ch * 8);
            if (!DROP_BL)
                cp16(d + 3 * TILE_B, Bgl + boff + ch * 8);
        }
        asm volatile("cp.async.commit_group;" ::: "memory");
    };

    float acc[4][4][4] = {};                 // [mt][nt][frag]

    const int nst = K / 32;
    prefetch(0, 0);

    for (int t = 0; t < nst; t++) {
        const bool more = (t + 1 < nst);
        if (more) prefetch(t + 1, (t + 1) & 1);
        if (more) asm volatile("cp.async.wait_group 1;" ::: "memory");
        else      asm volatile("cp.async.wait_group 0;" ::: "memory");
        __syncthreads();

        const uint32_t base = sbase + (t & 1) * STAGE_B;
        const uint32_t uAh = base, uAl = base + TILE_B;
        const uint32_t uBh = base + 2 * TILE_B, uBl = base + 3 * TILE_B;

        #pragma unroll
        for (int kk = 0; kk < 2; kk++) {
            const int kcol = kk * 16;
            uint32_t bh[4][2], bl[4][2];
            #pragma unroll
            for (int np = 0; np < 2; np++) {
                const uint32_t boff =
                    (uint32_t)((nBase + np * 16 + bRow) * (SROW * 2) +
                               (kcol + bCol8) * 2);
                uint32_t r4[4];
                ldm_x4(uBh + boff, r4);
                bh[np * 2][0] = r4[0]; bh[np * 2][1] = r4[1];
                bh[np * 2 + 1][0] = r4[2]; bh[np * 2 + 1][1] = r4[3];
                if (!DROP_BL) {
                    ldm_x4(uBl + boff, r4);
                    bl[np * 2][0] = r4[0]; bl[np * 2][1] = r4[1];
                    bl[np * 2 + 1][0] = r4[2]; bl[np * 2 + 1][1] = r4[3];
                }
            }
            #pragma unroll
            for (int mt = 0; mt < 4; mt++) {
                const uint32_t aoff =
                    (uint32_t)((mBase + mt * 16 + aRow) * (SROW * 2) +
                               (kcol + aCol8) * 2);
                uint32_t ah[4], al[4];
                ldm_x4(uAh + aoff, ah);
                ldm_x4(uAl + aoff, al);
                #pragma unroll
                for (int nt = 0; nt < 4; nt++) {
                    mma16816(acc[mt][nt], ah, bh[nt]);
                    if (!DROP_BL) mma16816(acc[mt][nt], ah, bl[nt]);
                    mma16816(acc[mt][nt], al, bh[nt]);
                }
            }
        }
        __syncthreads();
    }

    // ---------------- epilogue ----------------
    #pragma unroll
    for (int mt = 0; mt < 4; mt++) {
        #pragma unroll
        for (int nt = 0; nt < 4; nt++) {
            const int r0 = rowBase + mBase + mt * 16 + (lane >> 2);
            const int c0 = colBase + nBase + nt * 8 + 2 * (lane & 3);
            float2 o0, o1;
            o0.x = alpha * acc[mt][nt][0];
            o0.y = alpha * acc[mt][nt][1];
            o1.x = alpha * acc[mt][nt][2];
            o1.y = alpha * acc[mt][nt][3];
            if (HAS_BIAS) {
                const float2 bb = *reinterpret_cast<const float2*>(&bias[c0]);
                o0.x += bb.x; o0.y += bb.y;
                o1.x += bb.x; o1.y += bb.y;
            }
            if (SPLIT_OUT) {
                uint32_t h0, l0, h1, l1;
                split2(o0.x, o0.y, h0, l0);
                split2(o1.x, o1.y, h1, l1);
                *reinterpret_cast<uint32_t*>(&Ch[(size_t)r0 * Nc + c0]) = h0;
                *reinterpret_cast<uint32_t*>(&Cl[(size_t)r0 * Nc + c0]) = l0;
                *reinterpret_cast<uint32_t*>(&Ch[(size_t)(r0 + 8) * Nc + c0]) = h1;
                *reinterpret_cast<uint32_t*>(&Cl[(size_t)(r0 + 8) * Nc + c0]) = l1;
            } else {
                *reinterpret_cast<float2*>(&Cf[(size_t)r0 * Nc + c0]) = o0;
                *reinterpret_cast<float2*>(&Cf[(size_t)(r0 + 8) * Nc + c0]) = o1;
            }
        }
    }
}

// ---------------------------------------------------------------------------
// v[NSEQ,CDIM] fp32 -> vT[CDIM,NSEQ] fp16 hi/lo transpose (explicit mapping)
// ---------------------------------------------------------------------------
__global__ void __launch_bounds__(256)
transpose_split_kernel(const float* __restrict__ in,
                       __half* __restrict__ oh,
                       __half* __restrict__ ol)
{
    __shared__ float t[32][33];
    const int tid = threadIdx.y * 32 + threadIdx.x;
    const int c = blockIdx.x * 32 + threadIdx.x;     // CDIM index
    const int r = blockIdx.y * 32 + threadIdx.y;     // NSEQ index
    #pragma unroll
    for (int j = 0; j < 32; j += 8)
        t[threadIdx.y + j][threadIdx.x] = in[(size_t)(r + j) * CDIM + c];
    __syncthreads();
    #pragma unroll
    for (int i = 0; i < 2; i++) {
        const int p  = tid + i * 256;        // 0..511
        const int rr = p >> 4;               // cdim_local 0..31
        const int pc = p & 15;               // pair index along nseq
        const int r2 = blockIdx.x * 32 + rr;          // CDIM index
        const int c2 = blockIdx.y * 32 + pc * 2;      // NSEQ index (even)
        const float a = t[pc * 2][rr];
        const float b = t[pc * 2 + 1][rr];
        uint32_t h, l;
        split2(a, b, h, l);
        *reinterpret_cast<uint32_t*>(&oh[(size_t)r2 * NSEQ + c2]) = h;
        *reinterpret_cast<uint32_t*>(&ol[(size_t)r2 * NSEQ + c2]) = l;
    }
}

// ---------------------------------------------------------------------------
// Row softmax: read fp32 S row, write fp16 hi/lo probabilities.
// ---------------------------------------------------------------------------
__global__ void __launch_bounds__(256)
softmax_split_kernel(const float* __restrict__ S,
                     __half* __restrict__ Ph,
                     __half* __restrict__ Pl)
{
    const int row = blockIdx.x;
    const float4* p = reinterpret_cast<const float4*>(S + (size_t)row * NSEQ);
    uint2* ph = reinterpret_cast<uint2*>(Ph + (size_t)row * NSEQ);
    uint2* pl = reinterpret_cast<uint2*>(Pl + (size_t)row * NSEQ);
    const int tid = threadIdx.x;

    float4 v[8];
    float mx = -INFINITY;
    #pragma unroll
    for (int i = 0; i < 8; i++) {
        v[i] = p[tid + i * 256];
        mx = fmaxf(mx, fmaxf(fmaxf(v[i].x, v[i].y), fmaxf(v[i].z, v[i].w)));
    }

    __shared__ float red[8];
    __shared__ float bcast;
    const int lane = tid & 31, warp = tid >> 5;

    #pragma unroll
    for (int o = 16; o > 0; o >>= 1) mx = fmaxf(mx, __shfl_xor_sync(~0u, mx, o));
    if (lane == 0) red[warp] = mx;
    __syncthreads();
    if (warp == 0) {
        float m = (lane < 8) ? red[lane] : -INFINITY;
        #pragma unroll
        for (int o = 4; o > 0; o >>= 1) m = fmaxf(m, __shfl_xor_sync(~0u, m, o));
        if (lane == 0) bcast = m;
    }
    __syncthreads();
    mx = bcast;
    __syncthreads();

    float sum = 0.f;
    #pragma unroll
    for (int i = 0; i < 8; i++) {
        v[i].x = expf(v[i].x - mx);
        v[i].y = expf(v[i].y - mx);
        v[i].z = expf(v[i].z - mx);
        v[i].w = expf(v[i].w - mx);
        sum += v[i].x + v[i].y + v[i].z + v[i].w;
    }
    #pragma unroll
    for (int o = 16; o > 0; o >>= 1) sum += __shfl_xor_sync(~0u, sum, o);
    if (lane == 0) red[warp] = sum;
    __syncthreads();
    if (warp == 0) {
        float s = (lane < 8) ? red[lane] : 0.f;
        #pragma unroll
        for (int o = 4; o > 0; o >>= 1) s += __shfl_xor_sync(~0u, s, o);
        if (lane == 0) bcast = s;
    }
    __syncthreads();
    const float inv = 1.f / bcast;

    #pragma unroll
    for (int i = 0; i < 8; i++) {
        v[i].x *= inv; v[i].y *= inv; v[i].z *= inv; v[i].w *= inv;
        uint2 h, l;
        split4(v[i], h, l);
        ph[tid + i * 256] = h;
        pl[tid + i * 256] = l;
    }
}

// ---------------------------------------------------------------------------
// Launch
// ---------------------------------------------------------------------------
extern "C" void kernel_launch(void* const* d_in, const int* in_sizes, int n_in,
                              void* d_out, int out_size)
{
    const float* x  = (const float*)d_in[0];
    const float* Wq = (const float*)d_in[1];
    const float* bq = (const float*)d_in[2];
    const float* Wk = (const float*)d_in[3];
    const float* bk = (const float*)d_in[4];
    const float* Wv = (const float*)d_in[5];
    const float* bv = (const float*)d_in[6];
    const float* Wo = (const float*)d_in[7];
    const float* bo = (const float*)d_in[8];
    float* out = (float*)d_out;

    __half *xh, *xl, *Wqh, *Wql, *Wkh, *Wkl, *Wvh, *Wvl, *Woh, *Wol;
    __half *qh, *ql, *kh, *kl, *vTh, *vTl, *sh, *sl, *avh, *avl;
    float *v, *s;
    cudaGetSymbolAddress((void**)&xh,  g_xh);  cudaGetSymbolAddress((void**)&xl,  g_xl);
    cudaGetSymbolAddress((void**)&Wqh, g_Wqh); cudaGetSymbolAddress((void**)&Wql, g_Wql);
    cudaGetSymbolAddress((void**)&Wkh, g_Wkh); cudaGetSymbolAddress((void**)&Wkl, g_Wkl);
    cudaGetSymbolAddress((void**)&Wvh, g_Wvh); cudaGetSymbolAddress((void**)&Wvl, g_Wvl);
    cudaGetSymbolAddress((void**)&Woh, g_Woh); cudaGetSymbolAddress((void**)&Wol, g_Wol);
    cudaGetSymbolAddress((void**)&qh,  g_qh);  cudaGetSymbolAddress((void**)&ql,  g_ql);
    cudaGetSymbolAddress((void**)&kh,  g_kh);  cudaGetSymbolAddress((void**)&kl,  g_kl);
    cudaGetSymbolAddress((void**)&v,   g_v);
    cudaGetSymbolAddress((void**)&vTh, g_vTh); cudaGetSymbolAddress((void**)&vTl, g_vTl);
    cudaGetSymbolAddress((void**)&s,   g_s);
    cudaGetSymbolAddress((void**)&sh,  g_sh);  cudaGetSymbolAddress((void**)&sl,  g_sl);
    cudaGetSymbolAddress((void**)&avh, g_avh); cudaGetSymbolAddress((void**)&avl, g_avl);

    cudaFuncSetAttribute(hmma_gemm<true, true, false>,
                         cudaFuncAttributeMaxDynamicSharedMemorySize, SMEM_SZ);
    cudaFuncSetAttribute(hmma_gemm<true, false, true>,
                         cudaFuncAttributeMaxDynamicSharedMemorySize, SMEM_SZ);
    cudaFuncSetAttribute(hmma_gemm<false, false, false>,
                         cudaFuncAttributeMaxDynamicSharedMemorySize, SMEM_SZ);
    cudaFuncSetAttribute(hmma_gemm<false, true, true>,
                         cudaFuncAttributeMaxDynamicSharedMemorySize, SMEM_SZ);

    const float scale = 1.0f / sqrtf((float)HDIM);
    const dim3 blk(256);

    // ---- pre-split inputs ----
    split_kernel<<<(NSEQ * CDIM / 4 + 255) / 256, blk>>>(x,  xh,  xl,  NSEQ * CDIM / 4);
    split_kernel<<<(HDIM * CDIM / 4 + 255) / 256, blk>>>(Wq, Wqh, Wql, HDIM * CDIM / 4);
    split_kernel<<<(HDIM * CDIM / 4 + 255) / 256, blk>>>(Wk, Wkh, Wkl, HDIM * CDIM / 4);
    split_kernel<<<(CDIM * CDIM / 4 + 255) / 256, blk>>>(Wv, Wvh, Wvl, CDIM * CDIM / 4);
    split_kernel<<<(CDIM * CDIM / 4 + 255) / 256, blk>>>(Wo, Woh, Wol, CDIM * CDIM / 4);

    // ---- q, k: 3-pass, split out ----
    hmma_gemm<true, true, false><<<dim3(HDIM / 128, NSEQ / 128), blk, SMEM_SZ>>>(
        xh, xl, Wqh, Wql, bq, nullptr, qh, ql, NSEQ, HDIM, CDIM, 1.0f);
    hmma_gemm<true, true, false><<<dim3(HDIM / 128, NSEQ / 128), blk, SMEM_SZ>>>(
        xh, xl, Wkh, Wkl, bk, nullptr, kh, kl, NSEQ, HDIM, CDIM, 1.0f);
    // ---- v: 2-pass (drop Wv-lo), fp32 out ----
    hmma_gemm<true, false, true><<<dim3(CDIM / 128, NSEQ / 128), blk, SMEM_SZ>>>(
        xh, xl, Wvh, Wvl, bv, v, nullptr, nullptr, NSEQ, CDIM, CDIM, 1.0f);

    // ---- vT (split) ----
    transpose_split_kernel<<<dim3(CDIM / 32, NSEQ / 32), dim3(32, 8)>>>(v, vTh, vTl);

    // ---- S = scale * q @ k^T: 3-pass, fp32 out ----
    hmma_gemm<false, false, false><<<dim3(NSEQ / 128, NSEQ / 128), blk, SMEM_SZ>>>(
        qh, ql, kh, kl, nullptr, s, nullptr, nullptr, NSEQ, NSEQ, HDIM, scale);

    // ---- softmax -> split probs ----
    softmax_split_kernel<<<NSEQ, blk>>>(s, sh, sl);

    // ---- av = P @ vT^T: 2-pass (drop vT-lo), split out ----
    hmma_gemm<false, true, true><<<dim3(CDIM / 128, NSEQ / 128), blk, SMEM_SZ>>>(
        sh, sl, vTh, vTl, nullptr, nullptr, avh, avl, NSEQ, CDIM, NSEQ, 1.0f);

    // ---- out = av @ Wo^T + bo: 2-pass (drop Wo-lo), fp32 out ----
    hmma_gemm<true, false, true><<<dim3(CDIM / 128, NSEQ / 128), blk, SMEM_SZ>>>(
        avh, avl, Woh, Wol, bo, out, nullptr, nullptr, NSEQ, CDIM, CDIM, 1.0f);
}

// round 14
// speedup vs baseline: 4.2207x; 1.3277x over previous
#include <cuda_runtime.h>
#include <cuda_fp16.h>
#include <math.h>
#include <stdint.h>

#define NSEQ 8192
#define CDIM 1024
#define HDIM 128

// ---------------------------------------------------------------------------
// Scratch (__device__ globals; no cudaMalloc allowed). fp16 hi/lo operands.
// ---------------------------------------------------------------------------
__device__ __align__(256) __half g_xh [NSEQ * CDIM];
__device__ __align__(256) __half g_xl [NSEQ * CDIM];
__device__ __align__(256) __half g_Wqh[HDIM * CDIM];
__device__ __align__(256) __half g_Wql[HDIM * CDIM];
__device__ __align__(256) __half g_Wkh[HDIM * CDIM];
__device__ __align__(256) __half g_Wkl[HDIM * CDIM];
__device__ __align__(256) __half g_Wvh[CDIM * CDIM];
__device__ __align__(256) __half g_Wvl[CDIM * CDIM];
__device__ __align__(256) __half g_Woh[CDIM * CDIM];
__device__ __align__(256) __half g_Wol[CDIM * CDIM];
__device__ __align__(256) __half g_qh [NSEQ * HDIM];
__device__ __align__(256) __half g_ql [NSEQ * HDIM];
__device__ __align__(256) __half g_kh [NSEQ * HDIM];
__device__ __align__(256) __half g_kl [NSEQ * HDIM];
__device__ __align__(256) float  g_v  [NSEQ * CDIM];            // 32 MB
__device__ __align__(256) __half g_vTh[CDIM * NSEQ];
__device__ __align__(256) __half g_vTl[CDIM * NSEQ];
__device__ __align__(256) float  g_s  [(size_t)NSEQ * NSEQ];    // 256 MB
__device__ __align__(256) __half g_sh [(size_t)NSEQ * NSEQ];    // 128 MB
__device__ __align__(256) __half g_avh[NSEQ * CDIM];
__device__ __align__(256) __half g_avl[NSEQ * CDIM];

// ---------------------------------------------------------------------------
// Helpers (baseline PTX only; assembles for plain sm_103)
// ---------------------------------------------------------------------------
__device__ __forceinline__ uint32_t smem_u32(const void* p) {
    uint32_t a;
    asm("{ .reg .u64 t; cvta.to.shared.u64 t, %1; cvt.u32.u64 %0, t; }"
        : "=r"(a) : "l"(p));
    return a;
}
__device__ __forceinline__ void ldm_x4(uint32_t addr, uint32_t* r) {
    asm volatile("ldmatrix.sync.aligned.m8n8.x4.shared.b16 {%0,%1,%2,%3}, [%4];"
        : "=r"(r[0]), "=r"(r[1]), "=r"(r[2]), "=r"(r[3]) : "r"(addr));
}
__device__ __forceinline__ void mma16816(float* c, const uint32_t* a, const uint32_t* b) {
    asm volatile("mma.sync.aligned.m16n8k16.row.col.f32.f16.f16.f32 "
        "{%0,%1,%2,%3}, {%4,%5,%6,%7}, {%8,%9}, {%0,%1,%2,%3};"
        : "+f"(c[0]), "+f"(c[1]), "+f"(c[2]), "+f"(c[3])
        : "r"(a[0]), "r"(a[1]), "r"(a[2]), "r"(a[3]), "r"(b[0]), "r"(b[1]));
}
__device__ __forceinline__ void cp16(uint32_t dst, const void* src) {
    asm volatile("cp.async.cg.shared.global [%0], [%1], 16;"
        :: "r"(dst), "l"(src) : "memory");
}

// fp32 -> (hi fp16 rn, lo fp16 of exact residual), packed f16x2.
// PTX cvt f16x2: first source -> HIGH half, second -> LOW half.
__device__ __forceinline__ void split2(float a, float b, uint32_t& hi, uint32_t& lo) {
    asm("cvt.rn.f16x2.f32 %0, %1, %2;" : "=r"(hi) : "f"(b), "f"(a));
    __half2 h2 = *reinterpret_cast<__half2*>(&hi);
    float la = a - __low2float(h2);
    float lb = b - __high2float(h2);
    asm("cvt.rn.f16x2.f32 %0, %1, %2;" : "=r"(lo) : "f"(lb), "f"(la));
}
__device__ __forceinline__ void split4(const float4 v, uint2& hi, uint2& lo) {
    split2(v.x, v.y, hi.x, lo.x);
    split2(v.z, v.w, hi.y, lo.y);
}

// ---------------------------------------------------------------------------
// Elementwise fp32 -> fp16 hi/lo split
// ---------------------------------------------------------------------------
__global__ void __launch_bounds__(256)
split_kernel(const float* __restrict__ in, __half* __restrict__ oh,
             __half* __restrict__ ol, int n4)
{
    const int i = blockIdx.x * 256 + threadIdx.x;
    if (i >= n4) return;
    float4 v = reinterpret_cast<const float4*>(in)[i];
    uint2 h, l;
    split4(v, h, l);
    reinterpret_cast<uint2*>(oh)[i] = h;
    reinterpret_cast<uint2*>(ol)[i] = l;
}

// ---------------------------------------------------------------------------
// Split-fp16 HMMA GEMM, cp.async double-buffered, 2 CTAs/SM.
//   C = alpha * A[M,K] @ B[Nc,K]^T (+bias)
// CTA 128x128, BK=32, 256 threads, warps 2x4 (warp tile 64x32).
// Passes: AhBh (+ AhBl unless DROP_BL) (+ AlBh unless DROP_AL).
// SROW=40 keeps ldmatrix conflict-free.
// ---------------------------------------------------------------------------
#define SROW    40                         // fp16 per smem row (32 + 8 pad)
#define TILE_B  (128 * SROW * 2)           // 10240 B
#define STAGE_B (4 * TILE_B)               // Ah, Al, Bh, Bl = 40960 B
#define SMEM_SZ (2 * STAGE_B)              // double buffer = 81920 B

template <bool HAS_BIAS, bool SPLIT_OUT, bool DROP_BL, bool DROP_AL>
__global__ void __launch_bounds__(256, 2)
hmma_gemm(const __half* __restrict__ Agh, const __half* __restrict__ Agl,
          const __half* __restrict__ Bgh, const __half* __restrict__ Bgl,
          const float* __restrict__ bias,
          float* __restrict__ Cf,
          __half* __restrict__ Ch, __half* __restrict__ Cl,
          int M, int Nc, int K, float alpha)
{
    extern __shared__ __align__(256) char smem[];
    const uint32_t sbase = smem_u32(smem);

    const int tid  = threadIdx.x;
    const int warp = tid >> 5;
    const int lane = tid & 31;
    const int warp_m = warp >> 2;            // 0..1
    const int warp_n = warp & 3;             // 0..3
    const int mBase  = warp_m * 64;
    const int nBase  = warp_n * 32;

    const int rowBase = blockIdx.y * 128;
    const int colBase = blockIdx.x * 128;

    // ldmatrix per-lane offsets
    const int aRow  = (lane & 15);
    const int aCol8 = 8 * (lane >> 4);
    const int bg    = lane >> 3;             // 0..3
    const int bRow  = (lane & 7) + 8 * (bg >> 1);
    const int bCol8 = 8 * (bg & 1);

    // cp.async mapping: per tile 128 rows x 4 chunks of 16B
    const int cRow = tid >> 1;               // 0..127
    const int cCh0 = (tid & 1) * 2;          // chunks 0-1 or 2-3

    auto prefetch = [&](int t, int buf) {
        const uint32_t base = sbase + buf * STAGE_B;
        const int k0 = t * 32;
        const size_t aoff = (size_t)(rowBase + cRow) * K + k0;
        const size_t boff = (size_t)(colBase + cRow) * K + k0;
        #pragma unroll
        for (int c = 0; c < 2; c++) {
            const int ch = cCh0 + c;
            const uint32_t d = base + cRow * (SROW * 2) + ch * 16;
            cp16(d,              Agh + aoff + ch * 8);
            if (!DROP_AL)
                cp16(d + TILE_B, Agl + aoff + ch * 8);
            cp16(d + 2 * TILE_B, Bgh + boff + ch * 8);
            if (!DROP_BL)
                cp16(d + 3 * TILE_B, Bgl + boff + ch * 8);
        }
        asm volatile("cp.async.commit_group;" ::: "memory");
    };

    float acc[4][4][4] = {};                 // [mt][nt][frag]

    const int nst = K / 32;
    prefetch(0, 0);

    for (int t = 0; t < nst; t++) {
        const bool more = (t + 1 < nst);
        if (more) prefetch(t + 1, (t + 1) & 1);
        if (more) asm volatile("cp.async.wait_group 1;" ::: "memory");
        else      asm volatile("cp.async.wait_group 0;" ::: "memory");
        __syncthreads();

        const uint32_t base = sbase + (t & 1) * STAGE_B;
        const uint32_t uAh = base, uAl = base + TILE_B;
        const uint32_t uBh = base + 2 * TILE_B, uBl = base + 3 * TILE_B;

        #pragma unroll
        for (int kk = 0; kk < 2; kk++) {
            const int kcol = kk * 16;
            uint32_t bh[4][2], bl[4][2];
            #pragma unroll
            for (int np = 0; np < 2; np++) {
                const uint32_t boff =
                    (uint32_t)((nBase + np * 16 + bRow) * (SROW * 2) +
                               (kcol + bCol8) * 2);
                uint32_t r4[4];
                ldm_x4(uBh + boff, r4);
                bh[np * 2][0] = r4[0]; bh[np * 2][1] = r4[1];
                bh[np * 2 + 1][0] = r4[2]; bh[np * 2 + 1][1] = r4[3];
                if (!DROP_BL) {
                    ldm_x4(uBl + boff, r4);
                    bl[np * 2][0] = r4[0]; bl[np * 2][1] = r4[1];
                    bl[np * 2 + 1][0] = r4[2]; bl[np * 2 + 1][1] = r4[3];
                }
            }
            #pragma unroll
            for (int mt = 0; mt < 4; mt++) {
                const uint32_t aoff =
                    (uint32_t)((mBase + mt * 16 + aRow) * (SROW * 2) +
                               (kcol + aCol8) * 2);
                uint32_t ah[4], al[4];
                ldm_x4(uAh + aoff, ah);
                if (!DROP_AL) ldm_x4(uAl + aoff, al);
                #pragma unroll
                for (int nt = 0; nt < 4; nt++) {
                    mma16816(acc[mt][nt], ah, bh[nt]);
                    if (!DROP_BL) mma16816(acc[mt][nt], ah, bl[nt]);
                    if (!DROP_AL) mma16816(acc[mt][nt], al, bh[nt]);
                }
            }
        }
        __syncthreads();
    }

    // ---------------- epilogue ----------------
    #pragma unroll
    for (int mt = 0; mt < 4; mt++) {
        #pragma unroll
        for (int nt = 0; nt < 4; nt++) {
            const int r0 = rowBase + mBase + mt * 16 + (lane >> 2);
            const int c0 = colBase + nBase + nt * 8 + 2 * (lane & 3);
            float2 o0, o1;
            o0.x = alpha * acc[mt][nt][0];
            o0.y = alpha * acc[mt][nt][1];
            o1.x = alpha * acc[mt][nt][2];
            o1.y = alpha * acc[mt][nt][3];
            if (HAS_BIAS) {
                const float2 bb = *reinterpret_cast<const float2*>(&bias[c0]);
                o0.x += bb.x; o0.y += bb.y;
                o1.x += bb.x; o1.y += bb.y;
            }
            if (SPLIT_OUT) {
                uint32_t h0, l0, h1, l1;
                split2(o0.x, o0.y, h0, l0);
                split2(o1.x, o1.y, h1, l1);
                *reinterpret_cast<uint32_t*>(&Ch[(size_t)r0 * Nc + c0]) = h0;
                *reinterpret_cast<uint32_t*>(&Cl[(size_t)r0 * Nc + c0]) = l0;
                *reinterpret_cast<uint32_t*>(&Ch[(size_t)(r0 + 8) * Nc + c0]) = h1;
                *reinterpret_cast<uint32_t*>(&Cl[(size_t)(r0 + 8) * Nc + c0]) = l1;
            } else {
                *reinterpret_cast<float2*>(&Cf[(size_t)r0 * Nc + c0]) = o0;
                *reinterpret_cast<float2*>(&Cf[(size_t)(r0 + 8) * Nc + c0]) = o1;
            }
        }
    }
}

// ---------------------------------------------------------------------------
// v[NSEQ,CDIM] fp32 -> vT[CDIM,NSEQ] fp16 hi/lo transpose (explicit mapping)
// ---------------------------------------------------------------------------
__global__ void __launch_bounds__(256)
transpose_split_kernel(const float* __restrict__ in,
                       __half* __restrict__ oh,
                       __half* __restrict__ ol)
{
    __shared__ float t[32][33];
    const int tid = threadIdx.y * 32 + threadIdx.x;
    const int c = blockIdx.x * 32 + threadIdx.x;     // CDIM index
    const int r = blockIdx.y * 32 + threadIdx.y;     // NSEQ index
    #pragma unroll
    for (int j = 0; j < 32; j += 8)
        t[threadIdx.y + j][threadIdx.x] = in[(size_t)(r + j) * CDIM + c];
    __syncthreads();
    #pragma unroll
    for (int i = 0; i < 2; i++) {
        const int p  = tid + i * 256;        // 0..511
        const int rr = p >> 4;               // cdim_local 0..31
        const int pc = p & 15;               // pair index along nseq
        const int r2 = blockIdx.x * 32 + rr;          // CDIM index
        const int c2 = blockIdx.y * 32 + pc * 2;      // NSEQ index (even)
        const float a = t[pc * 2][rr];
        const float b = t[pc * 2 + 1][rr];
        uint32_t h, l;
        split2(a, b, h, l);
        *reinterpret_cast<uint32_t*>(&oh[(size_t)r2 * NSEQ + c2]) = h;
        *reinterpret_cast<uint32_t*>(&ol[(size_t)r2 * NSEQ + c2]) = l;
    }
}

// ---------------------------------------------------------------------------
// Row softmax: read fp32 S row, write fp16 probabilities (hi only).
// ---------------------------------------------------------------------------
__global__ void __launch_bounds__(256)
softmax_f16_kernel(const float* __restrict__ S, __half* __restrict__ Ph)
{
    const int row = blockIdx.x;
    const float4* p = reinterpret_cast<const float4*>(S + (size_t)row * NSEQ);
    uint2* ph = reinterpret_cast<uint2*>(Ph + (size_t)row * NSEQ);
    const int tid = threadIdx.x;

    float4 v[8];
    float mx = -INFINITY;
    #pragma unroll
    for (int i = 0; i < 8; i++) {
        v[i] = p[tid + i * 256];
        mx = fmaxf(mx, fmaxf(fmaxf(v[i].x, v[i].y), fmaxf(v[i].z, v[i].w)));
    }

    __shared__ float red[8];
    __shared__ float bcast;
    const int lane = tid & 31, warp = tid >> 5;

    #pragma unroll
    for (int o = 16; o > 0; o >>= 1) mx = fmaxf(mx, __shfl_xor_sync(~0u, mx, o));
    if (lane == 0) red[warp] = mx;
    __syncthreads();
    if (warp == 0) {
        float m = (lane < 8) ? red[lane] : -INFINITY;
        #pragma unroll
        for (int o = 4; o > 0; o >>= 1) m = fmaxf(m, __shfl_xor_sync(~0u, m, o));
        if (lane == 0) bcast = m;
    }
    __syncthreads();
    mx = bcast;
    __syncthreads();

    float sum = 0.f;
    #pragma unroll
    for (int i = 0; i < 8; i++) {
        v[i].x = expf(v[i].x - mx);
        v[i].y = expf(v[i].y - mx);
        v[i].z = expf(v[i].z - mx);
        v[i].w = expf(v[i].w - mx);
        sum += v[i].x + v[i].y + v[i].z + v[i].w;
    }
    #pragma unroll
    for (int o = 16; o > 0; o >>= 1) sum += __shfl_xor_sync(~0u, sum, o);
    if (lane == 0) red[warp] = sum;
    __syncthreads();
    if (warp == 0) {
        float s = (lane < 8) ? red[lane] : 0.f;
        #pragma unroll
        for (int o = 4; o > 0; o >>= 1) s += __shfl_xor_sync(~0u, s, o);
        if (lane == 0) bcast = s;
    }
    __syncthreads();
    const float inv = 1.f / bcast;

    #pragma unroll
    for (int i = 0; i < 8; i++) {
        uint2 h;
        asm("cvt.rn.f16x2.f32 %0, %1, %2;" : "=r"(h.x)
            : "f"(v[i].y * inv), "f"(v[i].x * inv));
        asm("cvt.rn.f16x2.f32 %0, %1, %2;" : "=r"(h.y)
            : "f"(v[i].w * inv), "f"(v[i].z * inv));
        ph[tid + i * 256] = h;
    }
}

// ---------------------------------------------------------------------------
// Launch
// ---------------------------------------------------------------------------
extern "C" void kernel_launch(void* const* d_in, const int* in_sizes, int n_in,
                              void* d_out, int out_size)
{
    const float* x  = (const float*)d_in[0];
    const float* Wq = (const float*)d_in[1];
    const float* bq = (const float*)d_in[2];
    const float* Wk = (const float*)d_in[3];
    const float* bk = (const float*)d_in[4];
    const float* Wv = (const float*)d_in[5];
    const float* bv = (const float*)d_in[6];
    const float* Wo = (const float*)d_in[7];
    const float* bo = (const float*)d_in[8];
    float* out = (float*)d_out;

    __half *xh, *xl, *Wqh, *Wql, *Wkh, *Wkl, *Wvh, *Wvl, *Woh, *Wol;
    __half *qh, *ql, *kh, *kl, *vTh, *vTl, *sh, *avh, *avl;
    float *v, *s;
    cudaGetSymbolAddress((void**)&xh,  g_xh);  cudaGetSymbolAddress((void**)&xl,  g_xl);
    cudaGetSymbolAddress((void**)&Wqh, g_Wqh); cudaGetSymbolAddress((void**)&Wql, g_Wql);
    cudaGetSymbolAddress((void**)&Wkh, g_Wkh); cudaGetSymbolAddress((void**)&Wkl, g_Wkl);
    cudaGetSymbolAddress((void**)&Wvh, g_Wvh); cudaGetSymbolAddress((void**)&Wvl, g_Wvl);
    cudaGetSymbolAddress((void**)&Woh, g_Woh); cudaGetSymbolAddress((void**)&Wol, g_Wol);
    cudaGetSymbolAddress((void**)&qh,  g_qh);  cudaGetSymbolAddress((void**)&ql,  g_ql);
    cudaGetSymbolAddress((void**)&kh,  g_kh);  cudaGetSymbolAddress((void**)&kl,  g_kl);
    cudaGetSymbolAddress((void**)&v,   g_v);
    cudaGetSymbolAddress((void**)&vTh, g_vTh); cudaGetSymbolAddress((void**)&vTl, g_vTl);
    cudaGetSymbolAddress((void**)&s,   g_s);
    cudaGetSymbolAddress((void**)&sh,  g_sh);
    cudaGetSymbolAddress((void**)&avh, g_avh); cudaGetSymbolAddress((void**)&avl, g_avl);

    cudaFuncSetAttribute(hmma_gemm<true, true, false, false>,
                         cudaFuncAttributeMaxDynamicSharedMemorySize, SMEM_SZ);
    cudaFuncSetAttribute(hmma_gemm<true, false, true, false>,
                         cudaFuncAttributeMaxDynamicSharedMemorySize, SMEM_SZ);
    cudaFuncSetAttribute(hmma_gemm<false, false, false, false>,
                         cudaFuncAttributeMaxDynamicSharedMemorySize, SMEM_SZ);
    cudaFuncSetAttribute(hmma_gemm<false, true, true, true>,
                         cudaFuncAttributeMaxDynamicSharedMemorySize, SMEM_SZ);

    const float scale = 1.0f / sqrtf((float)HDIM);
    const dim3 blk(256);

    // ---- pre-split inputs ----
    split_kernel<<<(NSEQ * CDIM / 4 + 255) / 256, blk>>>(x,  xh,  xl,  NSEQ * CDIM / 4);
    split_kernel<<<(HDIM * CDIM / 4 + 255) / 256, blk>>>(Wq, Wqh, Wql, HDIM * CDIM / 4);
    split_kernel<<<(HDIM * CDIM / 4 + 255) / 256, blk>>>(Wk, Wkh, Wkl, HDIM * CDIM / 4);
    split_kernel<<<(CDIM * CDIM / 4 + 255) / 256, blk>>>(Wv, Wvh, Wvl, CDIM * CDIM / 4);
    split_kernel<<<(CDIM * CDIM / 4 + 255) / 256, blk>>>(Wo, Woh, Wol, CDIM * CDIM / 4);

    // ---- q, k: 3-pass, split out ----
    hmma_gemm<true, true, false, false><<<dim3(HDIM / 128, NSEQ / 128), blk, SMEM_SZ>>>(
        xh, xl, Wqh, Wql, bq, nullptr, qh, ql, NSEQ, HDIM, CDIM, 1.0f);
    hmma_gemm<true, true, false, false><<<dim3(HDIM / 128, NSEQ / 128), blk, SMEM_SZ>>>(
        xh, xl, Wkh, Wkl, bk, nullptr, kh, kl, NSEQ, HDIM, CDIM, 1.0f);
    // ---- v: 2-pass (drop Wv-lo), fp32 out ----
    hmma_gemm<true, false, true, false><<<dim3(CDIM / 128, NSEQ / 128), blk, SMEM_SZ>>>(
        xh, xl, Wvh, Wvl, bv, v, nullptr, nullptr, NSEQ, CDIM, CDIM, 1.0f);

    // ---- vT (split) ----
    transpose_split_kernel<<<dim3(CDIM / 32, NSEQ / 32), dim3(32, 8)>>>(v, vTh, vTl);

    // ---- S = scale * q @ k^T: 3-pass, fp32 out ----
    hmma_gemm<false, false, false, false><<<dim3(NSEQ / 128, NSEQ / 128), blk, SMEM_SZ>>>(
        qh, ql, kh, kl, nullptr, s, nullptr, nullptr, NSEQ, NSEQ, HDIM, scale);

    // ---- softmax -> fp16 probs (hi only) ----
    softmax_f16_kernel<<<NSEQ, blk>>>(s, sh);

    // ---- av = P @ vT^T: 1-pass pure fp16, split out ----
    hmma_gemm<false, true, true, true><<<dim3(CDIM / 128, NSEQ / 128), blk, SMEM_SZ>>>(
        sh, nullptr, vTh, vTl, nullptr, nullptr, avh, avl, NSEQ, CDIM, NSEQ, 1.0f);

    // ---- out = av @ Wo^T + bo: 2-pass (drop Wo-lo), fp32 out ----
    hmma_gemm<true, false, true, false><<<dim3(CDIM / 128, NSEQ / 128), blk, SMEM_SZ>>>(
        avh, avl, Woh, Wol, bo, out, nullptr, nullptr, NSEQ, CDIM, CDIM, 1.0f);
}

// round 15
// speedup vs baseline: 4.4671x; 1.0584x over previous
#include <cuda_runtime.h>
#include <cuda_fp16.h>
#include <math.h>
#include <stdint.h>

#define NSEQ 8192
#define CDIM 1024
#define HDIM 128

// ---------------------------------------------------------------------------
// Scratch (__device__ globals; no cudaMalloc allowed). fp16 hi/lo operands.
// ---------------------------------------------------------------------------
__device__ __align__(256) __half g_xh [NSEQ * CDIM];
__device__ __align__(256) __half g_xl [NSEQ * CDIM];
__device__ __align__(256) __half g_Wqh[HDIM * CDIM];
__device__ __align__(256) __half g_Wql[HDIM * CDIM];
__device__ __align__(256) __half g_Wkh[HDIM * CDIM];
__device__ __align__(256) __half g_Wkl[HDIM * CDIM];
__device__ __align__(256) __half g_Wvh[CDIM * CDIM];
__device__ __align__(256) __half g_Wvl[CDIM * CDIM];
__device__ __align__(256) __half g_Woh[CDIM * CDIM];
__device__ __align__(256) __half g_Wol[CDIM * CDIM];
__device__ __align__(256) __half g_qh [NSEQ * HDIM];
__device__ __align__(256) __half g_ql [NSEQ * HDIM];
__device__ __align__(256) __half g_kh [NSEQ * HDIM];
__device__ __align__(256) __half g_kl [NSEQ * HDIM];
__device__ __align__(256) float  g_v  [NSEQ * CDIM];            // 32 MB
__device__ __align__(256) __half g_vTh[CDIM * NSEQ];
__device__ __align__(256) __half g_vTl[CDIM * NSEQ];
__device__ __align__(256) float  g_s  [(size_t)NSEQ * NSEQ];    // 256 MB
__device__ __align__(256) __half g_sh [(size_t)NSEQ * NSEQ];    // 128 MB
__device__ __align__(256) __half g_avh[NSEQ * CDIM];
__device__ __align__(256) __half g_avl[NSEQ * CDIM];

// ---------------------------------------------------------------------------
// Helpers (baseline PTX only; assembles for plain sm_103)
// ---------------------------------------------------------------------------
__device__ __forceinline__ uint32_t smem_u32(const void* p) {
    uint32_t a;
    asm("{ .reg .u64 t; cvta.to.shared.u64 t, %1; cvt.u32.u64 %0, t; }"
        : "=r"(a) : "l"(p));
    return a;
}
__device__ __forceinline__ void ldm_x4(uint32_t addr, uint32_t* r) {
    asm volatile("ldmatrix.sync.aligned.m8n8.x4.shared.b16 {%0,%1,%2,%3}, [%4];"
        : "=r"(r[0]), "=r"(r[1]), "=r"(r[2]), "=r"(r[3]) : "r"(addr));
}
__device__ __forceinline__ void mma16816(float* c, const uint32_t* a, const uint32_t* b) {
    asm volatile("mma.sync.aligned.m16n8k16.row.col.f32.f16.f16.f32 "
        "{%0,%1,%2,%3}, {%4,%5,%6,%7}, {%8,%9}, {%0,%1,%2,%3};"
        : "+f"(c[0]), "+f"(c[1]), "+f"(c[2]), "+f"(c[3])
        : "r"(a[0]), "r"(a[1]), "r"(a[2]), "r"(a[3]), "r"(b[0]), "r"(b[1]));
}
__device__ __forceinline__ void cp16(uint32_t dst, const void* src) {
    asm volatile("cp.async.cg.shared.global [%0], [%1], 16;"
        :: "r"(dst), "l"(src) : "memory");
}

// fp32 -> (hi fp16 rn, lo fp16 of exact residual), packed f16x2.
__device__ __forceinline__ void split2(float a, float b, uint32_t& hi, uint32_t& lo) {
    asm("cvt.rn.f16x2.f32 %0, %1, %2;" : "=r"(hi) : "f"(b), "f"(a));
    __half2 h2 = *reinterpret_cast<__half2*>(&hi);
    float la = a - __low2float(h2);
    float lb = b - __high2float(h2);
    asm("cvt.rn.f16x2.f32 %0, %1, %2;" : "=r"(lo) : "f"(lb), "f"(la));
}
__device__ __forceinline__ void split4(const float4 v, uint2& hi, uint2& lo) {
    split2(v.x, v.y, hi.x, lo.x);
    split2(v.z, v.w, hi.y, lo.y);
}

// ---------------------------------------------------------------------------
// Elementwise fp32 -> fp16 hi/lo split
// ---------------------------------------------------------------------------
__global__ void __launch_bounds__(256)
split_kernel(const float* __restrict__ in, __half* __restrict__ oh,
             __half* __restrict__ ol, int n4)
{
    const int i = blockIdx.x * 256 + threadIdx.x;
    if (i >= n4) return;
    float4 v = reinterpret_cast<const float4*>(in)[i];
    uint2 h, l;
    split4(v, h, l);
    reinterpret_cast<uint2*>(oh)[i] = h;
    reinterpret_cast<uint2*>(ol)[i] = l;
}

// ---------------------------------------------------------------------------
// Shared tiling constants
// ---------------------------------------------------------------------------
#define SROW    40                         // fp16 per smem row (32 + 8 pad)
#define TILE_B  (128 * SROW * 2)           // 10240 B
#define STAGE_B (4 * TILE_B)               // Ah, Al, Bh, Bl = 40960 B
#define SMEM_SZ (2 * STAGE_B)              // double buffer = 81920 B

// ---------------------------------------------------------------------------
// Generic split-fp16 HMMA GEMM (template pass control), 2 CTAs/SM.
//   C = alpha * A[M,K] @ B[Nc,K]^T (+bias)
// ---------------------------------------------------------------------------
template <bool HAS_BIAS, bool SPLIT_OUT, bool DROP_BL, bool DROP_AL>
__global__ void __launch_bounds__(256, 2)
hmma_gemm(const __half* __restrict__ Agh, const __half* __restrict__ Agl,
          const __half* __restrict__ Bgh, const __half* __restrict__ Bgl,
          const float* __restrict__ bias,
          float* __restrict__ Cf,
          __half* __restrict__ Ch, __half* __restrict__ Cl,
          int M, int Nc, int K, float alpha)
{
    extern __shared__ __align__(256) char smem[];
    const uint32_t sbase = smem_u32(smem);

    const int tid  = threadIdx.x;
    const int warp = tid >> 5;
    const int lane = tid & 31;
    const int warp_m = warp >> 2;
    const int warp_n = warp & 3;
    const int mBase  = warp_m * 64;
    const int nBase  = warp_n * 32;

    const int rowBase = blockIdx.y * 128;
    const int colBase = blockIdx.x * 128;

    const int aRow  = (lane & 15);
    const int aCol8 = 8 * (lane >> 4);
    const int bg    = lane >> 3;
    const int bRow  = (lane & 7) + 8 * (bg >> 1);
    const int bCol8 = 8 * (bg & 1);

    const int cRow = tid >> 1;
    const int cCh0 = (tid & 1) * 2;

    auto prefetch = [&](int t, int buf) {
        const uint32_t base = sbase + buf * STAGE_B;
        const int k0 = t * 32;
        const size_t aoff = (size_t)(rowBase + cRow) * K + k0;
        const size_t boff = (size_t)(colBase + cRow) * K + k0;
        #pragma unroll
        for (int c = 0; c < 2; c++) {
            const int ch = cCh0 + c;
            const uint32_t d = base + cRow * (SROW * 2) + ch * 16;
            cp16(d,              Agh + aoff + ch * 8);
            if (!DROP_AL)
                cp16(d + TILE_B, Agl + aoff + ch * 8);
            cp16(d + 2 * TILE_B, Bgh + boff + ch * 8);
            if (!DROP_BL)
                cp16(d + 3 * TILE_B, Bgl + boff + ch * 8);
        }
        asm volatile("cp.async.commit_group;" ::: "memory");
    };

    float acc[4][4][4] = {};

    const int nst = K / 32;
    prefetch(0, 0);

    for (int t = 0; t < nst; t++) {
        const bool more = (t + 1 < nst);
        if (more) prefetch(t + 1, (t + 1) & 1);
        if (more) asm volatile("cp.async.wait_group 1;" ::: "memory");
        else      asm volatile("cp.async.wait_group 0;" ::: "memory");
        __syncthreads();

        const uint32_t base = sbase + (t & 1) * STAGE_B;
        const uint32_t uAh = base, uAl = base + TILE_B;
        const uint32_t uBh = base + 2 * TILE_B, uBl = base + 3 * TILE_B;

        #pragma unroll
        for (int kk = 0; kk < 2; kk++) {
            const int kcol = kk * 16;
            uint32_t bh[4][2], bl[4][2];
            #pragma unroll
            for (int np = 0; np < 2; np++) {
                const uint32_t boff =
                    (uint32_t)((nBase + np * 16 + bRow) * (SROW * 2) +
                               (kcol + bCol8) * 2);
                uint32_t r4[4];
                ldm_x4(uBh + boff, r4);
                bh[np * 2][0] = r4[0]; bh[np * 2][1] = r4[1];
                bh[np * 2 + 1][0] = r4[2]; bh[np * 2 + 1][1] = r4[3];
                if (!DROP_BL) {
                    ldm_x4(uBl + boff, r4);
                    bl[np * 2][0] = r4[0]; bl[np * 2][1] = r4[1];
                    bl[np * 2 + 1][0] = r4[2]; bl[np * 2 + 1][1] = r4[3];
                }
            }
            #pragma unroll
            for (int mt = 0; mt < 4; mt++) {
                const uint32_t aoff =
                    (uint32_t)((mBase + mt * 16 + aRow) * (SROW * 2) +
                               (kcol + aCol8) * 2);
                uint32_t ah[4], al[4];
                ldm_x4(uAh + aoff, ah);
                if (!DROP_AL) ldm_x4(uAl + aoff, al);
                #pragma unroll
                for (int nt = 0; nt < 4; nt++) {
                    mma16816(acc[mt][nt], ah, bh[nt]);
                    if (!DROP_BL) mma16816(acc[mt][nt], ah, bl[nt]);
                    if (!DROP_AL) mma16816(acc[mt][nt], al, bh[nt]);
                }
            }
        }
        __syncthreads();
    }

    #pragma unroll
    for (int mt = 0; mt < 4; mt++) {
        #pragma unroll
        for (int nt = 0; nt < 4; nt++) {
            const int r0 = rowBase + mBase + mt * 16 + (lane >> 2);
            const int c0 = colBase + nBase + nt * 8 + 2 * (lane & 3);
            float2 o0, o1;
            o0.x = alpha * acc[mt][nt][0];
            o0.y = alpha * acc[mt][nt][1];
            o1.x = alpha * acc[mt][nt][2];
            o1.y = alpha * acc[mt][nt][3];
            if (HAS_BIAS) {
                const float2 bb = *reinterpret_cast<const float2*>(&bias[c0]);
                o0.x += bb.x; o0.y += bb.y;
                o1.x += bb.x; o1.y += bb.y;
            }
            if (SPLIT_OUT) {
                uint32_t h0, l0, h1, l1;
                split2(o0.x, o0.y, h0, l0);
                split2(o1.x, o1.y, h1, l1);
                *reinterpret_cast<uint32_t*>(&Ch[(size_t)r0 * Nc + c0]) = h0;
                *reinterpret_cast<uint32_t*>(&Cl[(size_t)r0 * Nc + c0]) = l0;
                *reinterpret_cast<uint32_t*>(&Ch[(size_t)(r0 + 8) * Nc + c0]) = h1;
                *reinterpret_cast<uint32_t*>(&Cl[(size_t)(r0 + 8) * Nc + c0]) = l1;
            } else {
                *reinterpret_cast<float2*>(&Cf[(size_t)r0 * Nc + c0]) = o0;
                *reinterpret_cast<float2*>(&Cf[(size_t)(r0 + 8) * Nc + c0]) = o1;
            }
        }
    }
}

// ---------------------------------------------------------------------------
// Fused q/k/v projection kernel. grid (10, NSEQ/128):
//   blockIdx.x 0..7 -> v tile (2-pass: AhBh + AlBh), fp32 out + bias
//   blockIdx.x == 8 -> q      (3-pass), split fp16 out + bias
//   blockIdx.x == 9 -> k      (3-pass), split fp16 out + bias
// A = x (split) for all; K = CDIM.
// ---------------------------------------------------------------------------
__global__ void __launch_bounds__(256, 2)
qkv_gemm(const __half* __restrict__ xh, const __half* __restrict__ xl,
         const __half* __restrict__ Wvh, const __half* __restrict__ Wvl,
         const float* __restrict__ bv, float* __restrict__ vout,
         const __half* __restrict__ Wqh, const __half* __restrict__ Wql,
         const float* __restrict__ bq,
         __half* __restrict__ qh, __half* __restrict__ ql,
         const __half* __restrict__ Wkh, const __half* __restrict__ Wkl,
         const float* __restrict__ bk,
         __half* __restrict__ kh, __half* __restrict__ kl)
{
    extern __shared__ __align__(256) char smem[];
    const uint32_t sbase = smem_u32(smem);
    const int K = CDIM;

    const int bx = blockIdx.x;
    const bool isV   = (bx < 8);
    const bool hasBL = !isV;                 // q/k need the B-lo pass

    const __half* Bh_; const __half* Bl_; const float* bias;
    __half* Ch_; __half* Cl_;
    int Nc, colBase;
    if (isV)          { Bh_ = Wvh; Bl_ = Wvl; bias = bv; Ch_ = nullptr; Cl_ = nullptr; Nc = CDIM; colBase = bx * 128; }
    else if (bx == 8) { Bh_ = Wqh; Bl_ = Wql; bias = bq; Ch_ = qh; Cl_ = ql; Nc = HDIM; colBase = 0; }
    else              { Bh_ = Wkh; Bl_ = Wkl; bias = bk; Ch_ = kh; Cl_ = kl; Nc = HDIM; colBase = 0; }

    const int tid  = threadIdx.x;
    const int warp = tid >> 5;
    const int lane = tid & 31;
    const int warp_m = warp >> 2;
    const int warp_n = warp & 3;
    const int mBase  = warp_m * 64;
    const int nBase  = warp_n * 32;
    const int rowBase = blockIdx.y * 128;

    const int aRow  = (lane & 15);
    const int aCol8 = 8 * (lane >> 4);
    const int bg    = lane >> 3;
    const int bRow  = (lane & 7) + 8 * (bg >> 1);
    const int bCol8 = 8 * (bg & 1);

    const int cRow = tid >> 1;
    const int cCh0 = (tid & 1) * 2;

    auto prefetch = [&](int t, int buf) {
        const uint32_t base = sbase + buf * STAGE_B;
        const int k0 = t * 32;
        const size_t aoff = (size_t)(rowBase + cRow) * K + k0;
        const size_t boff = (size_t)(colBase + cRow) * K + k0;
        #pragma unroll
        for (int c = 0; c < 2; c++) {
            const int ch = cCh0 + c;
            const uint32_t d = base + cRow * (SROW * 2) + ch * 16;
            cp16(d,              xh  + aoff + ch * 8);
            cp16(d + TILE_B,     xl  + aoff + ch * 8);
            cp16(d + 2 * TILE_B, Bh_ + boff + ch * 8);
            if (hasBL)
                cp16(d + 3 * TILE_B, Bl_ + boff + ch * 8);
        }
        asm volatile("cp.async.commit_group;" ::: "memory");
    };

    float acc[4][4][4] = {};

    const int nst = K / 32;
    prefetch(0, 0);

    for (int t = 0; t < nst; t++) {
        const bool more = (t + 1 < nst);
        if (more) prefetch(t + 1, (t + 1) & 1);
        if (more) asm volatile("cp.async.wait_group 1;" ::: "memory");
        else      asm volatile("cp.async.wait_group 0;" ::: "memory");
        __syncthreads();

        const uint32_t base = sbase + (t & 1) * STAGE_B;
        const uint32_t uAh = base, uAl = base + TILE_B;
        const uint32_t uBh = base + 2 * TILE_B, uBl = base + 3 * TILE_B;

        #pragma unroll
        for (int kk = 0; kk < 2; kk++) {
            const int kcol = kk * 16;
            uint32_t bh[4][2], bl[4][2];
            #pragma unroll
            for (int np = 0; np < 2; np++) {
                const uint32_t boff =
                    (uint32_t)((nBase + np * 16 + bRow) * (SROW * 2) +
                               (kcol + bCol8) * 2);
                uint32_t r4[4];
                ldm_x4(uBh + boff, r4);
                bh[np * 2][0] = r4[0]; bh[np * 2][1] = r4[1];
                bh[np * 2 + 1][0] = r4[2]; bh[np * 2 + 1][1] = r4[3];
                if (hasBL) {
                    ldm_x4(uBl + boff, r4);
                    bl[np * 2][0] = r4[0]; bl[np * 2][1] = r4[1];
                    bl[np * 2 + 1][0] = r4[2]; bl[np * 2 + 1][1] = r4[3];
                }
            }
            #pragma unroll
            for (int mt = 0; mt < 4; mt++) {
                const uint32_t aoff =
                    (uint32_t)((mBase + mt * 16 + aRow) * (SROW * 2) +
                               (kcol + aCol8) * 2);
                uint32_t ah[4], al[4];
                ldm_x4(uAh + aoff, ah);
                ldm_x4(uAl + aoff, al);
                #pragma unroll
                for (int nt = 0; nt < 4; nt++) {
                    mma16816(acc[mt][nt], ah, bh[nt]);
                    mma16816(acc[mt][nt], al, bh[nt]);
                    if (hasBL) mma16816(acc[mt][nt], ah, bl[nt]);
                }
            }
        }
        __syncthreads();
    }

    #pragma unroll
    for (int mt = 0; mt < 4; mt++) {
        #pragma unroll
        for (int nt = 0; nt < 4; nt++) {
            const int r0 = rowBase + mBase + mt * 16 + (lane >> 2);
            const int c0 = colBase + nBase + nt * 8 + 2 * (lane & 3);
            float2 o0, o1;
            o0.x = acc[mt][nt][0];
            o0.y = acc[mt][nt][1];
            o1.x = acc[mt][nt][2];
            o1.y = acc[mt][nt][3];
            const float2 bb = *reinterpret_cast<const float2*>(&bias[c0]);
            o0.x += bb.x; o0.y += bb.y;
            o1.x += bb.x; o1.y += bb.y;
            if (isV) {
                *reinterpret_cast<float2*>(&vout[(size_t)r0 * CDIM + c0]) = o0;
                *reinterpret_cast<float2*>(&vout[(size_t)(r0 + 8) * CDIM + c0]) = o1;
            } else {
                uint32_t h0, l0, h1, l1;
                split2(o0.x, o0.y, h0, l0);
                split2(o1.x, o1.y, h1, l1);
                *reinterpret_cast<uint32_t*>(&Ch_[(size_t)r0 * Nc + c0]) = h0;
                *reinterpret_cast<uint32_t*>(&Cl_[(size_t)r0 * Nc + c0]) = l0;
                *reinterpret_cast<uint32_t*>(&Ch_[(size_t)(r0 + 8) * Nc + c0]) = h1;
                *reinterpret_cast<uint32_t*>(&Cl_[(size_t)(r0 + 8) * Nc + c0]) = l1;
            }
        }
    }
}

// ---------------------------------------------------------------------------
// v[NSEQ,CDIM] fp32 -> vT[CDIM,NSEQ] fp16 hi/lo transpose (explicit mapping)
// ---------------------------------------------------------------------------
__global__ void __launch_bounds__(256)
transpose_split_kernel(const float* __restrict__ in,
                       __half* __restrict__ oh,
                       __half* __restrict__ ol)
{
    __shared__ float t[32][33];
    const int tid = threadIdx.y * 32 + threadIdx.x;
    const int c = blockIdx.x * 32 + threadIdx.x;     // CDIM index
    const int r = blockIdx.y * 32 + threadIdx.y;     // NSEQ index
    #pragma unroll
    for (int j = 0; j < 32; j += 8)
        t[threadIdx.y + j][threadIdx.x] = in[(size_t)(r + j) * CDIM + c];
    __syncthreads();
    #pragma unroll
    for (int i = 0; i < 2; i++) {
        const int p  = tid + i * 256;
        const int rr = p >> 4;
        const int pc = p & 15;
        const int r2 = blockIdx.x * 32 + rr;
        const int c2 = blockIdx.y * 32 + pc * 2;
        const float a = t[pc * 2][rr];
        const float b = t[pc * 2 + 1][rr];
        uint32_t h, l;
        split2(a, b, h, l);
        *reinterpret_cast<uint32_t*>(&oh[(size_t)r2 * NSEQ + c2]) = h;
        *reinterpret_cast<uint32_t*>(&ol[(size_t)r2 * NSEQ + c2]) = l;
    }
}

// ---------------------------------------------------------------------------
// Row softmax: read fp32 S row, write fp16 probabilities (hi only).
// ---------------------------------------------------------------------------
__global__ void __launch_bounds__(256)
softmax_f16_kernel(const float* __restrict__ S, __half* __restrict__ Ph)
{
    const int row = blockIdx.x;
    const float4* p = reinterpret_cast<const float4*>(S + (size_t)row * NSEQ);
    uint2* ph = reinterpret_cast<uint2*>(Ph + (size_t)row * NSEQ);
    const int tid = threadIdx.x;

    float4 v[8];
    float mx = -INFINITY;
    #pragma unroll
    for (int i = 0; i < 8; i++) {
        v[i] = p[tid + i * 256];
        mx = fmaxf(mx, fmaxf(fmaxf(v[i].x, v[i].y), fmaxf(v[i].z, v[i].w)));
    }

    __shared__ float red[8];
    __shared__ float bcast;
    const int lane = tid & 31, warp = tid >> 5;

    #pragma unroll
    for (int o = 16; o > 0; o >>= 1) mx = fmaxf(mx, __shfl_xor_sync(~0u, mx, o));
    if (lane == 0) red[warp] = mx;
    __syncthreads();
    if (warp == 0) {
        float m = (lane < 8) ? red[lane] : -INFINITY;
        #pragma unroll
        for (int o = 4; o > 0; o >>= 1) m = fmaxf(m, __shfl_xor_sync(~0u, m, o));
        if (lane == 0) bcast = m;
    }
    __syncthreads();
    mx = bcast;
    __syncthreads();

    float sum = 0.f;
    #pragma unroll
    for (int i = 0; i < 8; i++) {
        v[i].x = expf(v[i].x - mx);
        v[i].y = expf(v[i].y - mx);
        v[i].z = expf(v[i].z - mx);
        v[i].w = expf(v[i].w - mx);
        sum += v[i].x + v[i].y + v[i].z + v[i].w;
    }
    #pragma unroll
    for (int o = 16; o > 0; o >>= 1) sum += __shfl_xor_sync(~0u, sum, o);
    if (lane == 0) red[warp] = sum;
    __syncthreads();
    if (warp == 0) {
        float s = (lane < 8) ? red[lane] : 0.f;
        #pragma unroll
        for (int o = 4; o > 0; o >>= 1) s += __shfl_xor_sync(~0u, s, o);
        if (lane == 0) bcast = s;
    }
    __syncthreads();
    const float inv = 1.f / bcast;

    #pragma unroll
    for (int i = 0; i < 8; i++) {
        uint2 h;
        asm("cvt.rn.f16x2.f32 %0, %1, %2;" : "=r"(h.x)
            : "f"(v[i].y * inv), "f"(v[i].x * inv));
        asm("cvt.rn.f16x2.f32 %0, %1, %2;" : "=r"(h.y)
            : "f"(v[i].w * inv), "f"(v[i].z * inv));
        ph[tid + i * 256] = h;
    }
}

// ---------------------------------------------------------------------------
// Launch
// ---------------------------------------------------------------------------
extern "C" void kernel_launch(void* const* d_in, const int* in_sizes, int n_in,
                              void* d_out, int out_size)
{
    const float* x  = (const float*)d_in[0];
    const float* Wq = (const float*)d_in[1];
    const float* bq = (const float*)d_in[2];
    const float* Wk = (const float*)d_in[3];
    const float* bk = (const float*)d_in[4];
    const float* Wv = (const float*)d_in[5];
    const float* bv = (const float*)d_in[6];
    const float* Wo = (const float*)d_in[7];
    const float* bo = (const float*)d_in[8];
    float* out = (float*)d_out;

    __half *xh, *xl, *Wqh, *Wql, *Wkh, *Wkl, *Wvh, *Wvl, *Woh, *Wol;
    __half *qh, *ql, *kh, *kl, *vTh, *vTl, *sh, *avh, *avl;
    float *v, *s;
    cudaGetSymbolAddress((void**)&xh,  g_xh);  cudaGetSymbolAddress((void**)&xl,  g_xl);
    cudaGetSymbolAddress((void**)&Wqh, g_Wqh); cudaGetSymbolAddress((void**)&Wql, g_Wql);
    cudaGetSymbolAddress((void**)&Wkh, g_Wkh); cudaGetSymbolAddress((void**)&Wkl, g_Wkl);
    cudaGetSymbolAddress((void**)&Wvh, g_Wvh); cudaGetSymbolAddress((void**)&Wvl, g_Wvl);
    cudaGetSymbolAddress((void**)&Woh, g_Woh); cudaGetSymbolAddress((void**)&Wol, g_Wol);
    cudaGetSymbolAddress((void**)&qh,  g_qh);  cudaGetSymbolAddress((void**)&ql,  g_ql);
    cudaGetSymbolAddress((void**)&kh,  g_kh);  cudaGetSymbolAddress((void**)&kl,  g_kl);
    cudaGetSymbolAddress((void**)&v,   g_v);
    cudaGetSymbolAddress((void**)&vTh, g_vTh); cudaGetSymbolAddress((void**)&vTl, g_vTl);
    cudaGetSymbolAddress((void**)&s,   g_s);
    cudaGetSymbolAddress((void**)&sh,  g_sh);
    cudaGetSymbolAddress((void**)&avh, g_avh); cudaGetSymbolAddress((void**)&avl, g_avl);

    cudaFuncSetAttribute(qkv_gemm,
                         cudaFuncAttributeMaxDynamicSharedMemorySize, SMEM_SZ);
    cudaFuncSetAttribute(hmma_gemm<false, false, true, false>,
                         cudaFuncAttributeMaxDynamicSharedMemorySize, SMEM_SZ);
    cudaFuncSetAttribute(hmma_gemm<false, true, true, true>,
                         cudaFuncAttributeMaxDynamicSharedMemorySize, SMEM_SZ);
    cudaFuncSetAttribute(hmma_gemm<true, false, true, false>,
                         cudaFuncAttributeMaxDynamicSharedMemorySize, SMEM_SZ);

    const float scale = 1.0f / sqrtf((float)HDIM);
    const dim3 blk(256);

    // ---- pre-split inputs ----
    split_kernel<<<(NSEQ * CDIM / 4 + 255) / 256, blk>>>(x,  xh,  xl,  NSEQ * CDIM / 4);
    split_kernel<<<(HDIM * CDIM / 4 + 255) / 256, blk>>>(Wq, Wqh, Wql, HDIM * CDIM / 4);
    split_kernel<<<(HDIM * CDIM / 4 + 255) / 256, blk>>>(Wk, Wkh, Wkl, HDIM * CDIM / 4);
    split_kernel<<<(CDIM * CDIM / 4 + 255) / 256, blk>>>(Wv, Wvh, Wvl, CDIM * CDIM / 4);
    split_kernel<<<(CDIM * CDIM / 4 + 255) / 256, blk>>>(Wo, Woh, Wol, CDIM * CDIM / 4);

    // ---- fused q, k, v projections ----
    qkv_gemm<<<dim3(10, NSEQ / 128), blk, SMEM_SZ>>>(
        xh, xl, Wvh, Wvl, bv, v, Wqh, Wql, bq, qh, ql, Wkh, Wkl, bk, kh, kl);

    // ---- vT (split) ----
    transpose_split_kernel<<<dim3(CDIM / 32, NSEQ / 32), dim3(32, 8)>>>(v, vTh, vTl);

    // ---- S = scale * q @ k^T: 2-pass (drop k-lo), fp32 out ----
    hmma_gemm<false, false, true, false><<<dim3(NSEQ / 128, NSEQ / 128), blk, SMEM_SZ>>>(
        qh, ql, kh, kl, nullptr, s, nullptr, nullptr, NSEQ, NSEQ, HDIM, scale);

    // ---- softmax -> fp16 probs (hi only) ----
    softmax_f16_kernel<<<NSEQ, blk>>>(s, sh);

    // ---- av = P @ vT^T: 1-pass pure fp16, split out ----
    hmma_gemm<false, true, true, true><<<dim3(CDIM / 128, NSEQ / 128), blk, SMEM_SZ>>>(
        sh, nullptr, vTh, vTl, nullptr, nullptr, avh, avl, NSEQ, CDIM, NSEQ, 1.0f);

    // ---- out = av @ Wo^T + bo: 2-pass (drop Wo-lo), fp32 out ----
    hmma_gemm<true, false, true, false><<<dim3(CDIM / 128, NSEQ / 128), blk, SMEM_SZ>>>(
        avh, avl, Woh, Wol, bo, out, nullptr, nullptr, NSEQ, CDIM, CDIM, 1.0f);
}